// round 1
// baseline (speedup 1.0000x reference)
#include <cuda_runtime.h>
#include <math.h>

// ---------------- problem constants (fixed shapes) ----------------
#define Tn    2048          // tokens (B*S)
#define Hn    2048          // hidden
#define En    16            // routed experts
#define In    768           // moe intermediate
#define TWOI  1536          // 2*I
#define TOPK  4
#define RROWS (Tn*TOPK)     // 8192 packed rows (exact: every token -> 4 distinct experts)

// ---------------- device scratch (static, no allocation) ----------------
__device__ int   g_counts[En];
__device__ int   g_cursor[En];
__device__ int   g_offsets[En + 1];
__device__ int   g_rowTok[RROWS];          // packed row -> token
__device__ int   g_tokRow[Tn * TOPK];      // token,k -> packed row
__device__ float g_tokW[Tn * TOPK];        // token,k -> combine weight
__device__ int   g_tokExp[Tn * TOPK];      // token,k -> expert
__device__ float g_gu  [(size_t)RROWS * TWOI];  // routed gate_up output
__device__ float g_mid [(size_t)RROWS * In];    // routed silu(g)*u
__device__ float g_Yr  [(size_t)RROWS * Hn];    // routed down output (per packed row)
__device__ float g_gus [(size_t)Tn * TWOI];     // shared gate/up output
__device__ float g_mids[(size_t)Tn * In];       // shared silu(g)*u

// ---------------- init ----------------
__global__ void init_kernel() {
    int i = threadIdx.x;
    if (i < En) { g_counts[i] = 0; g_cursor[i] = 0; }
}

// ---------------- router: scores, sigmoid, top-4, weights ----------------
__global__ void router_kernel(const float* __restrict__ x,
                              const float* __restrict__ rw,
                              const float* __restrict__ eb) {
    __shared__ float sx[Hn];
    __shared__ float ssc[En];
    int t = blockIdx.x;
    const float* xr = x + (size_t)t * Hn;
    for (int i = threadIdx.x; i < Hn; i += blockDim.x) sx[i] = xr[i];
    __syncthreads();

    int w = threadIdx.x >> 5, l = threadIdx.x & 31;
    if (w < En) {
        const float* wr = rw + (size_t)w * Hn;
        float s = 0.f;
        #pragma unroll 8
        for (int i = l; i < Hn; i += 32) s += sx[i] * wr[i];
        #pragma unroll
        for (int o = 16; o > 0; o >>= 1) s += __shfl_down_sync(0xffffffffu, s, o);
        if (l == 0) ssc[w] = s;
    }
    __syncthreads();

    if (threadIdx.x == 0) {
        float sig[En], sel[En];
        #pragma unroll
        for (int e = 0; e < En; e++) {
            sig[e] = 1.f / (1.f + expf(-ssc[e]));
            sel[e] = sig[e] + eb[e];
        }
        int idx[TOPK];
        #pragma unroll
        for (int k = 0; k < TOPK; k++) {
            int best = 0; float bv = -1e30f;
            #pragma unroll
            for (int e = 0; e < En; e++)
                if (sel[e] > bv) { bv = sel[e]; best = e; }
            idx[k] = best; sel[best] = -1e30f;
        }
        float wsum = 0.f;
        #pragma unroll
        for (int k = 0; k < TOPK; k++) wsum += sig[idx[k]];
        float inv = 1.f / (wsum + 1e-20f);
        #pragma unroll
        for (int k = 0; k < TOPK; k++) {
            g_tokExp[t * TOPK + k] = idx[k];
            g_tokW[t * TOPK + k]   = sig[idx[k]] * inv;
            atomicAdd(&g_counts[idx[k]], 1);
        }
    }
}

// ---------------- prefix sum over 16 counts ----------------
__global__ void prefix_kernel() {
    g_offsets[0] = 0;
    for (int e = 0; e < En; e++) g_offsets[e + 1] = g_offsets[e] + g_counts[e];
}

// ---------------- scatter tokens into packed expert buckets ----------------
__global__ void scatter_kernel() {
    int t = blockIdx.x * blockDim.x + threadIdx.x;
    if (t >= Tn) return;
    #pragma unroll
    for (int k = 0; k < TOPK; k++) {
        int e = g_tokExp[t * TOPK + k];
        int pos = atomicAdd(&g_cursor[e], 1);
        int row = g_offsets[e] + pos;
        g_rowTok[row] = t;
        g_tokRow[t * TOPK + k] = row;
    }
}

// ---------------- generic tiled SGEMM: C[m, n] = A[m, :] . B[n, :] ----------------
// A: row-major [*, K] (rows optionally gathered via g_rowTok)
// B: row-major [N, K] weight (per-expert stride bStrideZ)
// Expert mode (useCounts=1): M = g_counts[z], rows packed from g_offsets[z].
#define BM 128
#define BN 64
#define BK 16

__global__ __launch_bounds__(256) void sgemm_kernel(
    const float* __restrict__ A, const float* __restrict__ B, float* __restrict__ C,
    int useGather, int useCounts, int fixedM,
    int K, int ldc, int ccol, size_t bStrideZ)
{
    int z = blockIdx.z;
    int M, rowbase;
    if (useCounts) { M = g_counts[z]; rowbase = g_offsets[z]; }
    else           { M = fixedM;      rowbase = 0; }
    int m0 = blockIdx.y * BM;
    if (m0 >= M) return;
    int n0 = blockIdx.x * BN;
    const float* Bz = B + (size_t)z * bStrideZ;

    __shared__ float As[BK][BM];
    __shared__ float Bs[BK][BN];

    int tid = threadIdx.x;
    int tx = tid & 15;    // n dir (16 * 4 = 64)
    int ty = tid >> 4;    // m dir (16 * 8 = 128)

    // hoist gathered A-row indices for this thread's 8 load slots
    int arow[8];
    #pragma unroll
    for (int i = 0; i < 8; i++) {
        int lin = tid + i * 256;
        int m = lin >> 4;
        int row = m0 + m;
        if (row < M) arow[i] = useGather ? g_rowTok[rowbase + row] : (rowbase + row);
        else         arow[i] = -1;
    }

    float acc[8][4];
    #pragma unroll
    for (int i = 0; i < 8; i++)
        #pragma unroll
        for (int j = 0; j < 4; j++) acc[i][j] = 0.f;

    for (int k0 = 0; k0 < K; k0 += BK) {
        #pragma unroll
        for (int i = 0; i < 8; i++) {
            int lin = tid + i * 256;
            int m = lin >> 4;
            int k = lin & 15;
            float v = 0.f;
            if (arow[i] >= 0) v = A[(size_t)arow[i] * K + k0 + k];
            As[k][m] = v;
        }
        #pragma unroll
        for (int i = 0; i < 4; i++) {
            int lin = tid + i * 256;
            int n = lin >> 4;
            int k = lin & 15;
            Bs[k][n] = Bz[(size_t)(n0 + n) * K + k0 + k];
        }
        __syncthreads();
        #pragma unroll
        for (int k = 0; k < BK; k++) {
            float rm[8], rn[4];
            #pragma unroll
            for (int i = 0; i < 8; i++) rm[i] = As[k][ty * 8 + i];
            #pragma unroll
            for (int j = 0; j < 4; j++) rn[j] = Bs[k][tx * 4 + j];
            #pragma unroll
            for (int i = 0; i < 8; i++)
                #pragma unroll
                for (int j = 0; j < 4; j++)
                    acc[i][j] += rm[i] * rn[j];
        }
        __syncthreads();
    }

    #pragma unroll
    for (int i = 0; i < 8; i++) {
        int m = m0 + ty * 8 + i;
        if (m < M) {
            size_t base = (size_t)(rowbase + m) * ldc + ccol + n0 + tx * 4;
            #pragma unroll
            for (int j = 0; j < 4; j++) C[base + j] = acc[i][j];
        }
    }
}

// ---------------- elementwise silu(g)*u ----------------
__global__ void silu_kernel(const float* __restrict__ gu, float* __restrict__ mid, int rows) {
    long i = (long)blockIdx.x * blockDim.x + threadIdx.x;
    long total = (long)rows * In;
    if (i >= total) return;
    int r = (int)(i / In);
    int c = (int)(i - (long)r * In);
    float g = gu[(size_t)r * TWOI + c];
    float u = gu[(size_t)r * TWOI + In + c];
    float s = g / (1.f + expf(-g));
    mid[i] = s * u;
}

// ---------------- combine: out[t] += sum_k w_k * Yr[row_k] ----------------
__global__ void combine_kernel(float* __restrict__ out) {
    int t = blockIdx.x;
    int r0 = g_tokRow[t * 4 + 0], r1 = g_tokRow[t * 4 + 1];
    int r2 = g_tokRow[t * 4 + 2], r3 = g_tokRow[t * 4 + 3];
    float w0 = g_tokW[t * 4 + 0], w1 = g_tokW[t * 4 + 1];
    float w2 = g_tokW[t * 4 + 2], w3 = g_tokW[t * 4 + 3];
    const float* y0 = g_Yr + (size_t)r0 * Hn;
    const float* y1 = g_Yr + (size_t)r1 * Hn;
    const float* y2 = g_Yr + (size_t)r2 * Hn;
    const float* y3 = g_Yr + (size_t)r3 * Hn;
    float* o = out + (size_t)t * Hn;
    for (int c = threadIdx.x; c < Hn; c += blockDim.x) {
        float v = o[c];
        v += w0 * y0[c] + w1 * y1[c] + w2 * y2[c] + w3 * y3[c];
        o[c] = v;
    }
}

// ---------------- launch ----------------
extern "C" void kernel_launch(void* const* d_in, const int* in_sizes, int n_in,
                              void* d_out, int out_size) {
    const float* x    = (const float*)d_in[0];  // [T, H]
    const float* rw   = (const float*)d_in[1];  // [E, H]
    const float* eb   = (const float*)d_in[2];  // [E]
    const float* gup  = (const float*)d_in[3];  // [E, 2I, H]
    const float* dwn  = (const float*)d_in[4];  // [E, H, I]
    const float* sgw  = (const float*)d_in[5];  // [IS, H]
    const float* suw  = (const float*)d_in[6];  // [IS, H]
    const float* sdw  = (const float*)d_in[7];  // [H, IS]
    float* out = (float*)d_out;

    void *p_gu, *p_mid, *p_Yr, *p_gus, *p_mids;
    cudaGetSymbolAddress(&p_gu,   g_gu);
    cudaGetSymbolAddress(&p_mid,  g_mid);
    cudaGetSymbolAddress(&p_Yr,   g_Yr);
    cudaGetSymbolAddress(&p_gus,  g_gus);
    cudaGetSymbolAddress(&p_mids, g_mids);

    init_kernel<<<1, 32>>>();
    router_kernel<<<Tn, 512>>>(x, rw, eb);
    prefix_kernel<<<1, 1>>>();
    scatter_kernel<<<(Tn + 255) / 256, 256>>>();

    // routed gate_up: C[8192,1536] = gathered x @ gup_e^T   (K=2048)
    sgemm_kernel<<<dim3(TWOI / BN, Tn / BM, En), 256>>>(
        x, gup, (float*)p_gu, /*gather=*/1, /*counts=*/1, 0,
        /*K=*/Hn, /*ldc=*/TWOI, /*ccol=*/0, /*bStrideZ=*/(size_t)TWOI * Hn);

    silu_kernel<<<(RROWS * In + 255) / 256, 256>>>((const float*)p_gu, (float*)p_mid, RROWS);

    // routed down: Yr[8192,2048] = mid @ dwn_e^T   (K=768)
    sgemm_kernel<<<dim3(Hn / BN, Tn / BM, En), 256>>>(
        (const float*)p_mid, dwn, (float*)p_Yr, /*gather=*/0, /*counts=*/1, 0,
        /*K=*/In, /*ldc=*/Hn, /*ccol=*/0, /*bStrideZ=*/(size_t)Hn * In);

    // shared gate -> gus[:, :768]
    sgemm_kernel<<<dim3(In / BN, Tn / BM, 1), 256>>>(
        x, sgw, (float*)p_gus, 0, 0, Tn, /*K=*/Hn, /*ldc=*/TWOI, /*ccol=*/0, 0);
    // shared up -> gus[:, 768:]
    sgemm_kernel<<<dim3(In / BN, Tn / BM, 1), 256>>>(
        x, suw, (float*)p_gus, 0, 0, Tn, /*K=*/Hn, /*ldc=*/TWOI, /*ccol=*/In, 0);

    silu_kernel<<<(Tn * In + 255) / 256, 256>>>((const float*)p_gus, (float*)p_mids, Tn);

    // shared down -> out (full overwrite of d_out)
    sgemm_kernel<<<dim3(Hn / BN, Tn / BM, 1), 256>>>(
        (const float*)p_mids, sdw, out, 0, 0, Tn, /*K=*/In, /*ldc=*/Hn, /*ccol=*/0, 0);

    // add routed contributions
    combine_kernel<<<Tn, 256>>>(out);
}

// round 3
// speedup vs baseline: 3.7572x; 3.7572x over previous
#include <cuda_runtime.h>
#include <math.h>
#include <stdint.h>

// ---------------- problem constants (fixed shapes) ----------------
#define Tn    2048
#define Hn    2048
#define En    16
#define In    768
#define TWOI  1536
#define TOPK  4
#define RROWS (Tn*TOPK)

// ---------------- device scratch ----------------
__device__ int   g_counts[En];
__device__ int   g_cursor[En];
__device__ int   g_offsets[En + 1];
__device__ int   g_rowTok[RROWS];
__device__ int   g_tokRow[Tn * TOPK];
__device__ float g_tokW[Tn * TOPK];
__device__ int   g_tokExp[Tn * TOPK];
__device__ float g_gu  [(size_t)RROWS * TWOI];
__device__ float g_mid [(size_t)RROWS * In];
__device__ float g_Yr  [(size_t)RROWS * Hn];
__device__ float g_gus [(size_t)Tn * TWOI];
__device__ float g_mids[(size_t)Tn * In];

__device__ __forceinline__ uint32_t f32_tf32(float f) {
    uint32_t r;
    asm("cvt.rna.tf32.f32 %0, %1;" : "=r"(r) : "f"(f));
    return r;
}

__device__ __forceinline__ void mma_tf32(float& d0, float& d1, float& d2, float& d3,
                                         uint32_t a0, uint32_t a1, uint32_t a2, uint32_t a3,
                                         uint32_t b0, uint32_t b1) {
    asm volatile(
        "mma.sync.aligned.m16n8k8.row.col.f32.tf32.tf32.f32 "
        "{%0,%1,%2,%3}, {%4,%5,%6,%7}, {%8,%9}, {%0,%1,%2,%3};"
        : "+f"(d0), "+f"(d1), "+f"(d2), "+f"(d3)
        : "r"(a0), "r"(a1), "r"(a2), "r"(a3), "r"(b0), "r"(b1));
}

// ---------------- init / router / prefix / scatter ----------------
__global__ void init_kernel() {
    int i = threadIdx.x;
    if (i < En) { g_counts[i] = 0; g_cursor[i] = 0; }
}

__global__ void router_kernel(const float* __restrict__ x,
                              const float* __restrict__ rw,
                              const float* __restrict__ eb) {
    __shared__ float sx[Hn];
    __shared__ float ssc[En];
    int t = blockIdx.x;
    const float* xr = x + (size_t)t * Hn;
    for (int i = threadIdx.x; i < Hn; i += blockDim.x) sx[i] = xr[i];
    __syncthreads();

    int w = threadIdx.x >> 5, l = threadIdx.x & 31;
    if (w < En) {
        const float* wr = rw + (size_t)w * Hn;
        float s = 0.f;
        #pragma unroll 8
        for (int i = l; i < Hn; i += 32) s += sx[i] * wr[i];
        #pragma unroll
        for (int o = 16; o > 0; o >>= 1) s += __shfl_down_sync(0xffffffffu, s, o);
        if (l == 0) ssc[w] = s;
    }
    __syncthreads();

    if (threadIdx.x == 0) {
        float sig[En], sel[En];
        #pragma unroll
        for (int e = 0; e < En; e++) {
            sig[e] = 1.f / (1.f + expf(-ssc[e]));
            sel[e] = sig[e] + eb[e];
        }
        int idx[TOPK];
        #pragma unroll
        for (int k = 0; k < TOPK; k++) {
            int best = 0; float bv = -1e30f;
            #pragma unroll
            for (int e = 0; e < En; e++)
                if (sel[e] > bv) { bv = sel[e]; best = e; }
            idx[k] = best; sel[best] = -1e30f;
        }
        float wsum = 0.f;
        #pragma unroll
        for (int k = 0; k < TOPK; k++) wsum += sig[idx[k]];
        float inv = 1.f / (wsum + 1e-20f);
        #pragma unroll
        for (int k = 0; k < TOPK; k++) {
            g_tokExp[t * TOPK + k] = idx[k];
            g_tokW[t * TOPK + k]   = sig[idx[k]] * inv;
            atomicAdd(&g_counts[idx[k]], 1);
        }
    }
}

__global__ void prefix_kernel() {
    g_offsets[0] = 0;
    for (int e = 0; e < En; e++) g_offsets[e + 1] = g_offsets[e] + g_counts[e];
}

__global__ void scatter_kernel() {
    int t = blockIdx.x * blockDim.x + threadIdx.x;
    if (t >= Tn) return;
    #pragma unroll
    for (int k = 0; k < TOPK; k++) {
        int e = g_tokExp[t * TOPK + k];
        int pos = atomicAdd(&g_cursor[e], 1);
        int row = g_offsets[e] + pos;
        g_rowTok[row] = t;
        g_tokRow[t * TOPK + k] = row;
    }
}

// ---------------- tf32 mma.sync GEMM: C[m,n] = A[m,:] . B[n,:] ----------------
// CTA tile 128x256x32, 8 warps (2 m x 4 n), warp tile 64x64.
// SMEM: 128B rows (32 tf32), XOR swizzle g' = g ^ (row&7) -> conflict-free STS/LDS.
#define BM_ 128
#define BN_ 256
#define BK_ 32
#define ABYTES (BM_ * BK_ * 4)          // 16384
#define BBYTES (BN_ * BK_ * 4)          // 32768
#define STAGEB (ABYTES + BBYTES)        // 49152
#define SMTOT  (2 * STAGEB)             // 98304

__global__ __launch_bounds__(256) void tmma_kernel(
    const float* __restrict__ A, const float* __restrict__ B, float* __restrict__ C,
    int useGather, int useCounts, int fixedM,
    int K, int ldc, int ccol, size_t bStrideZ)
{
    extern __shared__ char smem[];
    int z = blockIdx.z;
    int M, rowbase;
    if (useCounts) { M = g_counts[z]; rowbase = g_offsets[z]; }
    else           { M = fixedM;      rowbase = 0; }
    int m0 = blockIdx.y * BM_;
    if (m0 >= M) return;
    int n0 = blockIdx.x * BN_;
    const float* Bz = B + (size_t)z * bStrideZ;

    const int tid = threadIdx.x;
    const int wid = tid >> 5, lane = tid & 31;
    const int q = lane >> 2, e = lane & 3;
    const int wm = wid & 1, wn = wid >> 1;     // 2 x 4 warp grid

    // ---- producer setup ----
    // A: 1024 float4 slots (row 0..127, group 0..7), 4 per thread
    const float* aptr[4];
    uint32_t asts[4];
    #pragma unroll
    for (int i = 0; i < 4; i++) {
        int slot = tid + i * 256;
        int row = slot >> 3, g = slot & 7;
        int gr = m0 + row;
        if (gr < M) {
            int src = useGather ? g_rowTok[rowbase + gr] : (rowbase + gr);
            aptr[i] = A + (size_t)src * K + g * 4;
        } else aptr[i] = nullptr;
        asts[i] = (uint32_t)(row * 128 + ((g ^ (row & 7)) << 4));
    }
    // B: 2048 float4 slots (row 0..255, group 0..7), 8 per thread
    const float* bptr[8];
    uint32_t bsts[8];
    #pragma unroll
    for (int i = 0; i < 8; i++) {
        int slot = tid + i * 256;
        int row = slot >> 3, g = slot & 7;
        bptr[i] = Bz + (size_t)(n0 + row) * K + g * 4;
        bsts[i] = (uint32_t)(ABYTES + row * 128 + ((g ^ (row & 7)) << 4));
    }

    float acc[4][8][4];
    #pragma unroll
    for (int i = 0; i < 4; i++)
        #pragma unroll
        for (int j = 0; j < 8; j++)
            #pragma unroll
            for (int v = 0; v < 4; v++) acc[i][j][v] = 0.f;

    const int nk = K / BK_;
    uint4 ra[4], rb[8];

    // ---- prologue: ktile 0 load+store, ktile 1 load ----
    #pragma unroll
    for (int i = 0; i < 4; i++) {
        if (aptr[i]) {
            float4 f = *reinterpret_cast<const float4*>(aptr[i]);
            ra[i] = make_uint4(f32_tf32(f.x), f32_tf32(f.y), f32_tf32(f.z), f32_tf32(f.w));
        } else ra[i] = make_uint4(0u, 0u, 0u, 0u);
    }
    #pragma unroll
    for (int i = 0; i < 8; i++) {
        float4 f = *reinterpret_cast<const float4*>(bptr[i]);
        rb[i] = make_uint4(f32_tf32(f.x), f32_tf32(f.y), f32_tf32(f.z), f32_tf32(f.w));
    }
    #pragma unroll
    for (int i = 0; i < 4; i++) *reinterpret_cast<uint4*>(smem + asts[i]) = ra[i];
    #pragma unroll
    for (int i = 0; i < 8; i++) *reinterpret_cast<uint4*>(smem + bsts[i]) = rb[i];

    if (nk > 1) {
        #pragma unroll
        for (int i = 0; i < 4; i++) {
            if (aptr[i]) {
                float4 f = *reinterpret_cast<const float4*>(aptr[i] + BK_);
                ra[i] = make_uint4(f32_tf32(f.x), f32_tf32(f.y), f32_tf32(f.z), f32_tf32(f.w));
            } else ra[i] = make_uint4(0u, 0u, 0u, 0u);
        }
        #pragma unroll
        for (int i = 0; i < 8; i++) {
            float4 f = *reinterpret_cast<const float4*>(bptr[i] + BK_);
            rb[i] = make_uint4(f32_tf32(f.x), f32_tf32(f.y), f32_tf32(f.z), f32_tf32(f.w));
        }
    }
    __syncthreads();

    // ---- mainloop ----
    for (int kt = 0; kt < nk; kt++) {
        const char* As = smem + (kt & 1) * STAGEB;
        const char* Bs = As + ABYTES;

        // consumer base addresses (row&7 == q throughout)
        const char* aBase = As + ((wm * 64 + q) * 128 + e * 4);
        const char* bBase = Bs + ((wn * 64 + q) * 128 + e * 4);

        #pragma unroll
        for (int s = 0; s < 4; s++) {
            uint32_t af[4][4];
            #pragma unroll
            for (int i = 0; i < 4; i++) {
                const char* p = aBase + i * 16 * 128;
                int g0 = ((2 * s)     ^ q) << 4;
                int g1 = ((2 * s + 1) ^ q) << 4;
                af[i][0] = *reinterpret_cast<const uint32_t*>(p + g0);
                af[i][1] = *reinterpret_cast<const uint32_t*>(p + g0 + 8 * 128);
                af[i][2] = *reinterpret_cast<const uint32_t*>(p + g1);
                af[i][3] = *reinterpret_cast<const uint32_t*>(p + g1 + 8 * 128);
            }
            #pragma unroll
            for (int jn = 0; jn < 8; jn++) {
                const char* p = bBase + jn * 8 * 128;
                uint32_t b0 = *reinterpret_cast<const uint32_t*>(p + (((2 * s)     ^ q) << 4));
                uint32_t b1 = *reinterpret_cast<const uint32_t*>(p + (((2 * s + 1) ^ q) << 4));
                #pragma unroll
                for (int i = 0; i < 4; i++)
                    mma_tf32(acc[i][jn][0], acc[i][jn][1], acc[i][jn][2], acc[i][jn][3],
                             af[i][0], af[i][1], af[i][2], af[i][3], b0, b1);
            }
        }

        if (kt + 1 < nk) {
            __syncthreads();   // all warps done reading buf[(kt+1)&1] (ktile kt-1)
            char* dst = smem + ((kt + 1) & 1) * STAGEB;
            #pragma unroll
            for (int i = 0; i < 4; i++) *reinterpret_cast<uint4*>(dst + asts[i]) = ra[i];
            #pragma unroll
            for (int i = 0; i < 8; i++) *reinterpret_cast<uint4*>(dst + bsts[i]) = rb[i];
            if (kt + 2 < nk) {
                int k0 = (kt + 2) * BK_;
                #pragma unroll
                for (int i = 0; i < 4; i++) {
                    if (aptr[i]) {
                        float4 f = *reinterpret_cast<const float4*>(aptr[i] + k0);
                        ra[i] = make_uint4(f32_tf32(f.x), f32_tf32(f.y), f32_tf32(f.z), f32_tf32(f.w));
                    } else ra[i] = make_uint4(0u, 0u, 0u, 0u);
                }
                #pragma unroll
                for (int i = 0; i < 8; i++) {
                    float4 f = *reinterpret_cast<const float4*>(bptr[i] + k0);
                    rb[i] = make_uint4(f32_tf32(f.x), f32_tf32(f.y), f32_tf32(f.z), f32_tf32(f.w));
                }
            }
            __syncthreads();   // new stage visible
        }
    }

    // ---- epilogue: acc -> C ----
    #pragma unroll
    for (int i = 0; i < 4; i++) {
        int r0 = m0 + wm * 64 + i * 16 + q;
        int r1 = r0 + 8;
        #pragma unroll
        for (int jn = 0; jn < 8; jn++) {
            int cc = ccol + n0 + wn * 64 + jn * 8 + 2 * e;
            if (r0 < M) {
                float2 v = make_float2(acc[i][jn][0], acc[i][jn][1]);
                *reinterpret_cast<float2*>(C + (size_t)(rowbase + r0) * ldc + cc) = v;
            }
            if (r1 < M) {
                float2 v = make_float2(acc[i][jn][2], acc[i][jn][3]);
                *reinterpret_cast<float2*>(C + (size_t)(rowbase + r1) * ldc + cc) = v;
            }
        }
    }
}

// ---------------- elementwise silu(g)*u ----------------
__global__ void silu_kernel(const float* __restrict__ gu, float* __restrict__ mid, int rows) {
    long i = (long)blockIdx.x * blockDim.x + threadIdx.x;
    long total = (long)rows * In;
    if (i >= total) return;
    int r = (int)(i / In);
    int c = (int)(i - (long)r * In);
    float g = gu[(size_t)r * TWOI + c];
    float u = gu[(size_t)r * TWOI + In + c];
    float s = g / (1.f + expf(-g));
    mid[i] = s * u;
}

// ---------------- combine ----------------
__global__ void combine_kernel(float* __restrict__ out) {
    int t = blockIdx.x;
    int r0 = g_tokRow[t * 4 + 0], r1 = g_tokRow[t * 4 + 1];
    int r2 = g_tokRow[t * 4 + 2], r3 = g_tokRow[t * 4 + 3];
    float w0 = g_tokW[t * 4 + 0], w1 = g_tokW[t * 4 + 1];
    float w2 = g_tokW[t * 4 + 2], w3 = g_tokW[t * 4 + 3];
    const float* y0 = g_Yr + (size_t)r0 * Hn;
    const float* y1 = g_Yr + (size_t)r1 * Hn;
    const float* y2 = g_Yr + (size_t)r2 * Hn;
    const float* y3 = g_Yr + (size_t)r3 * Hn;
    float* o = out + (size_t)t * Hn;
    for (int c = threadIdx.x; c < Hn; c += blockDim.x) {
        float v = o[c];
        v += w0 * y0[c] + w1 * y1[c] + w2 * y2[c] + w3 * y3[c];
        o[c] = v;
    }
}

// ---------------- launch ----------------
extern "C" void kernel_launch(void* const* d_in, const int* in_sizes, int n_in,
                              void* d_out, int out_size) {
    const float* x    = (const float*)d_in[0];
    const float* rw   = (const float*)d_in[1];
    const float* eb   = (const float*)d_in[2];
    const float* gup  = (const float*)d_in[3];
    const float* dwn  = (const float*)d_in[4];
    const float* sgw  = (const float*)d_in[5];
    const float* suw  = (const float*)d_in[6];
    const float* sdw  = (const float*)d_in[7];
    float* out = (float*)d_out;

    static int smem_set = 0;
    if (!smem_set) {
        cudaFuncSetAttribute(tmma_kernel, cudaFuncAttributeMaxDynamicSharedMemorySize, SMTOT);
        smem_set = 1;
    }

    void *p_gu, *p_mid, *p_Yr, *p_gus, *p_mids;
    cudaGetSymbolAddress(&p_gu,   g_gu);
    cudaGetSymbolAddress(&p_mid,  g_mid);
    cudaGetSymbolAddress(&p_Yr,   g_Yr);
    cudaGetSymbolAddress(&p_gus,  g_gus);
    cudaGetSymbolAddress(&p_mids, g_mids);

    init_kernel<<<1, 32>>>();
    router_kernel<<<Tn, 512>>>(x, rw, eb);
    prefix_kernel<<<1, 1>>>();
    scatter_kernel<<<(Tn + 255) / 256, 256>>>();

    // routed gate_up: [8192,1536] = gather(x) @ gup_e^T   (K=2048)
    tmma_kernel<<<dim3(TWOI / BN_, Tn / BM_, En), 256, SMTOT>>>(
        x, gup, (float*)p_gu, 1, 1, 0, Hn, TWOI, 0, (size_t)TWOI * Hn);

    silu_kernel<<<(RROWS * In + 255) / 256, 256>>>((const float*)p_gu, (float*)p_mid, RROWS);

    // routed down: [8192,2048] = mid @ dwn_e^T   (K=768)
    tmma_kernel<<<dim3(Hn / BN_, Tn / BM_, En), 256, SMTOT>>>(
        (const float*)p_mid, dwn, (float*)p_Yr, 0, 1, 0, In, Hn, 0, (size_t)Hn * In);

    // shared gate -> gus[:, :768]
    tmma_kernel<<<dim3(In / BN_, Tn / BM_, 1), 256, SMTOT>>>(
        x, sgw, (float*)p_gus, 0, 0, Tn, Hn, TWOI, 0, 0);
    // shared up -> gus[:, 768:]
    tmma_kernel<<<dim3(In / BN_, Tn / BM_, 1), 256, SMTOT>>>(
        x, suw, (float*)p_gus, 0, 0, Tn, Hn, TWOI, In, 0);

    silu_kernel<<<(Tn * In + 255) / 256, 256>>>((const float*)p_gus, (float*)p_mids, Tn);

    // shared down -> out
    tmma_kernel<<<dim3(Hn / BN_, Tn / BM_, 1), 256, SMTOT>>>(
        (const float*)p_mids, sdw, out, 0, 0, Tn, In, Hn, 0, 0);

    combine_kernel<<<Tn, 256>>>(out);
}

// round 4
// speedup vs baseline: 5.7227x; 1.5231x over previous
#include <cuda_runtime.h>
#include <math.h>
#include <stdint.h>

// ---------------- problem constants (fixed shapes) ----------------
#define Tn    2048
#define Hn    2048
#define En    16
#define In    768
#define TWOI  1536
#define TOPK  4
#define RROWS (Tn*TOPK)

// ---------------- device scratch ----------------
__device__ int   g_counts[En];
__device__ int   g_cursor[En];
__device__ int   g_offsets[En + 1];
__device__ int   g_rowTok[RROWS];
__device__ int   g_tokRow[Tn * TOPK];
__device__ float g_tokW[Tn * TOPK];
__device__ int   g_tokExp[Tn * TOPK];
__device__ float g_gu  [(size_t)RROWS * TWOI];
__device__ float g_mid [(size_t)RROWS * In];
__device__ float g_Yr  [(size_t)RROWS * Hn];
__device__ float g_gus [(size_t)Tn * TWOI];
__device__ float g_mids[(size_t)Tn * In];
// tf32-rounded operand copies
__device__ float g_xtf  [(size_t)Tn * Hn];
__device__ float g_guptf[(size_t)En * TWOI * Hn];
__device__ float g_dwntf[(size_t)En * Hn * In];
__device__ float g_sgwtf[(size_t)In * Hn];
__device__ float g_suwtf[(size_t)In * Hn];
__device__ float g_sdwtf[(size_t)Hn * In];

__device__ __forceinline__ uint32_t f32_tf32(float f) {
    uint32_t r;
    asm("cvt.rna.tf32.f32 %0, %1;" : "=r"(r) : "f"(f));
    return r;
}

__device__ __forceinline__ uint32_t smem_u32(const void* p) {
    uint32_t a;
    asm("{ .reg .u64 t; cvta.to.shared.u64 t, %1; cvt.u32.u64 %0, t; }" : "=r"(a) : "l"(p));
    return a;
}

__device__ __forceinline__ void cp_async16(uint32_t dst, const void* src) {
    asm volatile("cp.async.cg.shared.global [%0], [%1], 16;" :: "r"(dst), "l"(src) : "memory");
}
#define CP_COMMIT() asm volatile("cp.async.commit_group;" ::: "memory")
#define CP_WAIT(n)  asm volatile("cp.async.wait_group %0;" :: "n"(n) : "memory")

__device__ __forceinline__ void mma_tf32(float& d0, float& d1, float& d2, float& d3,
                                         uint32_t a0, uint32_t a1, uint32_t a2, uint32_t a3,
                                         uint32_t b0, uint32_t b1) {
    asm volatile(
        "mma.sync.aligned.m16n8k8.row.col.f32.tf32.tf32.f32 "
        "{%0,%1,%2,%3}, {%4,%5,%6,%7}, {%8,%9}, {%0,%1,%2,%3};"
        : "+f"(d0), "+f"(d1), "+f"(d2), "+f"(d3)
        : "r"(a0), "r"(a1), "r"(a2), "r"(a3), "r"(b0), "r"(b1));
}

// ---------------- tf32 conversion pass ----------------
__global__ void tf32conv_kernel(const float4* __restrict__ in, float4* __restrict__ out, int n4) {
    int stride = gridDim.x * blockDim.x;
    for (int i = blockIdx.x * blockDim.x + threadIdx.x; i < n4; i += stride) {
        float4 f = in[i];
        uint4 v = make_uint4(f32_tf32(f.x), f32_tf32(f.y), f32_tf32(f.z), f32_tf32(f.w));
        out[i] = make_float4(__uint_as_float(v.x), __uint_as_float(v.y),
                             __uint_as_float(v.z), __uint_as_float(v.w));
    }
}

// ---------------- init / router / prefix / scatter ----------------
__global__ void init_kernel() {
    int i = threadIdx.x;
    if (i < En) { g_counts[i] = 0; g_cursor[i] = 0; }
}

__global__ void router_kernel(const float* __restrict__ x,
                              const float* __restrict__ rw,
                              const float* __restrict__ eb) {
    __shared__ float sx[Hn];
    __shared__ float ssc[En];
    int t = blockIdx.x;
    const float* xr = x + (size_t)t * Hn;
    for (int i = threadIdx.x; i < Hn; i += blockDim.x) sx[i] = xr[i];
    __syncthreads();

    int w = threadIdx.x >> 5, l = threadIdx.x & 31;
    if (w < En) {
        const float* wr = rw + (size_t)w * Hn;
        float s = 0.f;
        #pragma unroll 8
        for (int i = l; i < Hn; i += 32) s += sx[i] * wr[i];
        #pragma unroll
        for (int o = 16; o > 0; o >>= 1) s += __shfl_down_sync(0xffffffffu, s, o);
        if (l == 0) ssc[w] = s;
    }
    __syncthreads();

    if (threadIdx.x == 0) {
        float sig[En], sel[En];
        #pragma unroll
        for (int e = 0; e < En; e++) {
            sig[e] = 1.f / (1.f + expf(-ssc[e]));
            sel[e] = sig[e] + eb[e];
        }
        int idx[TOPK];
        #pragma unroll
        for (int k = 0; k < TOPK; k++) {
            int best = 0; float bv = -1e30f;
            #pragma unroll
            for (int e = 0; e < En; e++)
                if (sel[e] > bv) { bv = sel[e]; best = e; }
            idx[k] = best; sel[best] = -1e30f;
        }
        float wsum = 0.f;
        #pragma unroll
        for (int k = 0; k < TOPK; k++) wsum += sig[idx[k]];
        float inv = 1.f / (wsum + 1e-20f);
        #pragma unroll
        for (int k = 0; k < TOPK; k++) {
            g_tokExp[t * TOPK + k] = idx[k];
            g_tokW[t * TOPK + k]   = sig[idx[k]] * inv;
            atomicAdd(&g_counts[idx[k]], 1);
        }
    }
}

__global__ void prefix_kernel() {
    g_offsets[0] = 0;
    for (int e = 0; e < En; e++) g_offsets[e + 1] = g_offsets[e] + g_counts[e];
}

__global__ void scatter_kernel() {
    int t = blockIdx.x * blockDim.x + threadIdx.x;
    if (t >= Tn) return;
    #pragma unroll
    for (int k = 0; k < TOPK; k++) {
        int e = g_tokExp[t * TOPK + k];
        int pos = atomicAdd(&g_cursor[e], 1);
        int row = g_offsets[e] + pos;
        g_rowTok[row] = t;
        g_tokRow[t * TOPK + k] = row;
    }
}

// ---------------- tf32 mma.sync GEMM, cp.async 4-stage pipeline ----------------
// CTA tile 128x256x32, 8 warps (2m x 4n), warp tile 64x64.
// SMEM rows 128B (32 tf32), XOR swizzle g' = g ^ (row&7): conflict-free STS/LDS.
// Inputs MUST already be tf32-rounded fp32 bits (cp.async copies raw).
#define BM_ 128
#define BN_ 256
#define BK_ 32
#define ABYTES (BM_ * BK_ * 4)          // 16384
#define BBYTES (BN_ * BK_ * 4)          // 32768
#define STAGEB (ABYTES + BBYTES)        // 49152
#define NSTAGE 4
#define SMTOT  (NSTAGE * STAGEB)        // 196608

__global__ __launch_bounds__(256) void tmma_kernel(
    const float* __restrict__ A, const float* __restrict__ B, float* __restrict__ C,
    int useGather, int useCounts, int fixedM,
    int K, int ldc, int ccol, size_t bStrideZ)
{
    extern __shared__ char smem[];
    int z = blockIdx.z;
    int M, rowbase;
    if (useCounts) { M = g_counts[z]; rowbase = g_offsets[z]; }
    else           { M = fixedM;      rowbase = 0; }
    int m0 = blockIdx.y * BM_;
    if (m0 >= M) return;
    int n0 = blockIdx.x * BN_;
    const float* Bz = B + (size_t)z * bStrideZ;

    const int tid = threadIdx.x;
    const int wid = tid >> 5, lane = tid & 31;
    const int q = lane >> 2, e = lane & 3;
    const int wm = wid & 1, wn = wid >> 1;
    const uint32_t sbase = smem_u32(smem);

    // ---- producer setup: A 4 slots, B 8 slots of 16B per thread ----
    const float* aptr[4];
    uint32_t adst[4];
    #pragma unroll
    for (int i = 0; i < 4; i++) {
        int slot = tid + i * 256;
        int row = slot >> 3, g = slot & 7;
        int gr = m0 + row;
        int cl = gr < M ? gr : (M - 1);              // clamp: garbage rows masked at store
        int src = useGather ? g_rowTok[rowbase + cl] : (rowbase + cl);
        aptr[i] = A + (size_t)src * K + g * 4;
        adst[i] = sbase + (uint32_t)(row * 128 + ((g ^ (row & 7)) << 4));
    }
    const float* bptr[8];
    uint32_t bdst[8];
    #pragma unroll
    for (int i = 0; i < 8; i++) {
        int slot = tid + i * 256;
        int row = slot >> 3, g = slot & 7;
        bptr[i] = Bz + (size_t)(n0 + row) * K + g * 4;
        bdst[i] = sbase + (uint32_t)(ABYTES + row * 128 + ((g ^ (row & 7)) << 4));
    }

    float acc[4][8][4];
    #pragma unroll
    for (int i = 0; i < 4; i++)
        #pragma unroll
        for (int j = 0; j < 8; j++)
            #pragma unroll
            for (int v = 0; v < 4; v++) acc[i][j][v] = 0.f;

    const int nk = K / BK_;   // >= 24 always

    // ---- prologue: stages 0..NSTAGE-2 ----
    #pragma unroll
    for (int s = 0; s < NSTAGE - 1; s++) {
        uint32_t so = (uint32_t)(s * STAGEB);
        int k0 = s * BK_;
        #pragma unroll
        for (int i = 0; i < 4; i++) cp_async16(adst[i] + so, aptr[i] + k0);
        #pragma unroll
        for (int i = 0; i < 8; i++) cp_async16(bdst[i] + so, bptr[i] + k0);
        CP_COMMIT();
    }

    // ---- mainloop ----
    for (int kt = 0; kt < nk; kt++) {
        CP_WAIT(NSTAGE - 2);
        __syncthreads();

        // issue stage kt+NSTAGE-1 (overwrites slot of consumed stage kt-1)
        int ns = kt + NSTAGE - 1;
        if (ns < nk) {
            uint32_t so = (uint32_t)((ns & (NSTAGE - 1)) * STAGEB);
            int k0 = ns * BK_;
            #pragma unroll
            for (int i = 0; i < 4; i++) cp_async16(adst[i] + so, aptr[i] + k0);
            #pragma unroll
            for (int i = 0; i < 8; i++) cp_async16(bdst[i] + so, bptr[i] + k0);
        }
        CP_COMMIT();

        const char* As = smem + (kt & (NSTAGE - 1)) * STAGEB;
        const char* Bs = As + ABYTES;
        const char* aBase = As + ((wm * 64 + q) * 128 + e * 4);
        const char* bBase = Bs + ((wn * 64 + q) * 128 + e * 4);

        #pragma unroll
        for (int s = 0; s < 4; s++) {
            uint32_t af[4][4];
            int g0 = ((2 * s)     ^ q) << 4;
            int g1 = ((2 * s + 1) ^ q) << 4;
            #pragma unroll
            for (int i = 0; i < 4; i++) {
                const char* p = aBase + i * 16 * 128;
                af[i][0] = *reinterpret_cast<const uint32_t*>(p + g0);
                af[i][1] = *reinterpret_cast<const uint32_t*>(p + g0 + 8 * 128);
                af[i][2] = *reinterpret_cast<const uint32_t*>(p + g1);
                af[i][3] = *reinterpret_cast<const uint32_t*>(p + g1 + 8 * 128);
            }
            #pragma unroll
            for (int jn = 0; jn < 8; jn++) {
                const char* p = bBase + jn * 8 * 128;
                uint32_t b0 = *reinterpret_cast<const uint32_t*>(p + g0);
                uint32_t b1 = *reinterpret_cast<const uint32_t*>(p + g1);
                #pragma unroll
                for (int i = 0; i < 4; i++)
                    mma_tf32(acc[i][jn][0], acc[i][jn][1], acc[i][jn][2], acc[i][jn][3],
                             af[i][0], af[i][1], af[i][2], af[i][3], b0, b1);
            }
        }
    }

    // ---- epilogue ----
    #pragma unroll
    for (int i = 0; i < 4; i++) {
        int r0 = m0 + wm * 64 + i * 16 + q;
        int r1 = r0 + 8;
        #pragma unroll
        for (int jn = 0; jn < 8; jn++) {
            int cc = ccol + n0 + wn * 64 + jn * 8 + 2 * e;
            if (r0 < M) {
                float2 v = make_float2(acc[i][jn][0], acc[i][jn][1]);
                *reinterpret_cast<float2*>(C + (size_t)(rowbase + r0) * ldc + cc) = v;
            }
            if (r1 < M) {
                float2 v = make_float2(acc[i][jn][2], acc[i][jn][3]);
                *reinterpret_cast<float2*>(C + (size_t)(rowbase + r1) * ldc + cc) = v;
            }
        }
    }
}

// ---------------- elementwise silu(g)*u -> tf32-rounded output ----------------
__global__ void silu_kernel(const float* __restrict__ gu, float* __restrict__ mid, int rows) {
    long i = (long)blockIdx.x * blockDim.x + threadIdx.x;
    long total = (long)rows * In;
    if (i >= total) return;
    int r = (int)(i / In);
    int c = (int)(i - (long)r * In);
    float g = gu[(size_t)r * TWOI + c];
    float u = gu[(size_t)r * TWOI + In + c];
    float s = g / (1.f + expf(-g));
    mid[i] = __uint_as_float(f32_tf32(s * u));
}

// ---------------- combine ----------------
__global__ void combine_kernel(float* __restrict__ out) {
    int t = blockIdx.x;
    int r0 = g_tokRow[t * 4 + 0], r1 = g_tokRow[t * 4 + 1];
    int r2 = g_tokRow[t * 4 + 2], r3 = g_tokRow[t * 4 + 3];
    float w0 = g_tokW[t * 4 + 0], w1 = g_tokW[t * 4 + 1];
    float w2 = g_tokW[t * 4 + 2], w3 = g_tokW[t * 4 + 3];
    const float* y0 = g_Yr + (size_t)r0 * Hn;
    const float* y1 = g_Yr + (size_t)r1 * Hn;
    const float* y2 = g_Yr + (size_t)r2 * Hn;
    const float* y3 = g_Yr + (size_t)r3 * Hn;
    float* o = out + (size_t)t * Hn;
    for (int c = threadIdx.x; c < Hn; c += blockDim.x) {
        float v = o[c];
        v += w0 * y0[c] + w1 * y1[c] + w2 * y2[c] + w3 * y3[c];
        o[c] = v;
    }
}

// ---------------- launch ----------------
extern "C" void kernel_launch(void* const* d_in, const int* in_sizes, int n_in,
                              void* d_out, int out_size) {
    const float* x    = (const float*)d_in[0];
    const float* rw   = (const float*)d_in[1];
    const float* eb   = (const float*)d_in[2];
    const float* gup  = (const float*)d_in[3];
    const float* dwn  = (const float*)d_in[4];
    const float* sgw  = (const float*)d_in[5];
    const float* suw  = (const float*)d_in[6];
    const float* sdw  = (const float*)d_in[7];
    float* out = (float*)d_out;

    static int smem_set = 0;
    if (!smem_set) {
        cudaFuncSetAttribute(tmma_kernel, cudaFuncAttributeMaxDynamicSharedMemorySize, SMTOT);
        smem_set = 1;
    }

    void *p_gu, *p_mid, *p_Yr, *p_gus, *p_mids;
    void *p_xtf, *p_guptf, *p_dwntf, *p_sgwtf, *p_suwtf, *p_sdwtf;
    cudaGetSymbolAddress(&p_gu,    g_gu);
    cudaGetSymbolAddress(&p_mid,   g_mid);
    cudaGetSymbolAddress(&p_Yr,    g_Yr);
    cudaGetSymbolAddress(&p_gus,   g_gus);
    cudaGetSymbolAddress(&p_mids,  g_mids);
    cudaGetSymbolAddress(&p_xtf,   g_xtf);
    cudaGetSymbolAddress(&p_guptf, g_guptf);
    cudaGetSymbolAddress(&p_dwntf, g_dwntf);
    cudaGetSymbolAddress(&p_sgwtf, g_sgwtf);
    cudaGetSymbolAddress(&p_suwtf, g_suwtf);
    cudaGetSymbolAddress(&p_sdwtf, g_sdwtf);

    init_kernel<<<1, 32>>>();
    router_kernel<<<Tn, 512>>>(x, rw, eb);
    prefix_kernel<<<1, 1>>>();
    scatter_kernel<<<(Tn + 255) / 256, 256>>>();

    // tf32-round all GEMM operands (cp.async path copies raw bits)
    const int CVB = 512, CVG = 1024;
    tf32conv_kernel<<<CVG, CVB>>>((const float4*)x,   (float4*)p_xtf,   Tn * Hn / 4);
    tf32conv_kernel<<<CVG, CVB>>>((const float4*)gup, (float4*)p_guptf, En * TWOI * Hn / 4);
    tf32conv_kernel<<<CVG, CVB>>>((const float4*)dwn, (float4*)p_dwntf, En * Hn * In / 4);
    tf32conv_kernel<<<CVG, CVB>>>((const float4*)sgw, (float4*)p_sgwtf, In * Hn / 4);
    tf32conv_kernel<<<CVG, CVB>>>((const float4*)suw, (float4*)p_suwtf, In * Hn / 4);
    tf32conv_kernel<<<CVG, CVB>>>((const float4*)sdw, (float4*)p_sdwtf, Hn * In / 4);

    // routed gate_up: [8192,1536] = gather(x_tf) @ gup_tf^T   (K=2048)
    tmma_kernel<<<dim3(TWOI / BN_, Tn / BM_, En), 256, SMTOT>>>(
        (const float*)p_xtf, (const float*)p_guptf, (float*)p_gu,
        1, 1, 0, Hn, TWOI, 0, (size_t)TWOI * Hn);

    silu_kernel<<<(RROWS * In + 255) / 256, 256>>>((const float*)p_gu, (float*)p_mid, RROWS);

    // routed down: [8192,2048] = mid @ dwn_tf^T   (K=768)
    tmma_kernel<<<dim3(Hn / BN_, Tn / BM_, En), 256, SMTOT>>>(
        (const float*)p_mid, (const float*)p_dwntf, (float*)p_Yr,
        0, 1, 0, In, Hn, 0, (size_t)Hn * In);

    // shared gate / up -> gus
    tmma_kernel<<<dim3(In / BN_, Tn / BM_, 1), 256, SMTOT>>>(
        (const float*)p_xtf, (const float*)p_sgwtf, (float*)p_gus,
        0, 0, Tn, Hn, TWOI, 0, 0);
    tmma_kernel<<<dim3(In / BN_, Tn / BM_, 1), 256, SMTOT>>>(
        (const float*)p_xtf, (const float*)p_suwtf, (float*)p_gus,
        0, 0, Tn, Hn, TWOI, In, 0);

    silu_kernel<<<(Tn * In + 255) / 256, 256>>>((const float*)p_gus, (float*)p_mids, Tn);

    // shared down -> out
    tmma_kernel<<<dim3(Hn / BN_, Tn / BM_, 1), 256, SMTOT>>>(
        (const float*)p_mids, (const float*)p_sdwtf, out,
        0, 0, Tn, In, Hn, 0, 0);

    combine_kernel<<<Tn, 256>>>(out);
}

// round 5
// speedup vs baseline: 9.4621x; 1.6534x over previous
#include <cuda_runtime.h>
#include <cuda_fp16.h>
#include <math.h>
#include <stdint.h>

// ---------------- problem constants (fixed shapes) ----------------
#define Tn    2048
#define Hn    2048
#define En    16
#define In    768
#define TWOI  1536
#define TOPK  4
#define RROWS (Tn*TOPK)

// ---------------- device scratch ----------------
__device__ int   g_counts[En];
__device__ int   g_cursor[En];
__device__ int   g_offsets[En + 1];
__device__ int   g_rowTok[RROWS];
__device__ int   g_tokRow[Tn * TOPK];
__device__ float g_tokW[Tn * TOPK];
__device__ int   g_tokExp[Tn * TOPK];
__device__ float g_gu  [(size_t)RROWS * TWOI];   // routed gate_up out (fp32)
__device__ __half g_mid [(size_t)RROWS * In];    // silu(g)*u (fp16)
__device__ float g_Yr  [(size_t)RROWS * Hn];     // routed down out (fp32)
__device__ float g_gus [(size_t)Tn * TWOI];      // shared gate/up out (fp32)
__device__ __half g_mids[(size_t)Tn * In];       // shared silu (fp16)
// fp16 operand copies
__device__ __half g_xh  [(size_t)Tn * Hn];
__device__ __half g_guph[(size_t)En * TWOI * Hn];
__device__ __half g_dwnh[(size_t)En * Hn * In];
__device__ __half g_sgwh[(size_t)In * Hn];
__device__ __half g_suwh[(size_t)In * Hn];
__device__ __half g_sdwh[(size_t)Hn * In];

__device__ __forceinline__ uint32_t smem_u32(const void* p) {
    uint32_t a;
    asm("{ .reg .u64 t; cvta.to.shared.u64 t, %1; cvt.u32.u64 %0, t; }" : "=r"(a) : "l"(p));
    return a;
}

__device__ __forceinline__ void cp_async16(uint32_t dst, const void* src) {
    asm volatile("cp.async.cg.shared.global [%0], [%1], 16;" :: "r"(dst), "l"(src) : "memory");
}
#define CP_COMMIT() asm volatile("cp.async.commit_group;" ::: "memory")
#define CP_WAIT(n)  asm volatile("cp.async.wait_group %0;" :: "n"(n) : "memory")

__device__ __forceinline__ void mma_f16(float& d0, float& d1, float& d2, float& d3,
                                        uint32_t a0, uint32_t a1, uint32_t a2, uint32_t a3,
                                        uint32_t b0, uint32_t b1) {
    asm volatile(
        "mma.sync.aligned.m16n8k16.row.col.f32.f16.f16.f32 "
        "{%0,%1,%2,%3}, {%4,%5,%6,%7}, {%8,%9}, {%0,%1,%2,%3};"
        : "+f"(d0), "+f"(d1), "+f"(d2), "+f"(d3)
        : "r"(a0), "r"(a1), "r"(a2), "r"(a3), "r"(b0), "r"(b1));
}

// ---------------- fp32 -> fp16 conversion pass ----------------
__global__ void h16conv_kernel(const float4* __restrict__ in, uint2* __restrict__ out, int n4) {
    int stride = gridDim.x * blockDim.x;
    for (int i = blockIdx.x * blockDim.x + threadIdx.x; i < n4; i += stride) {
        float4 f = in[i];
        __half2 h0 = __floats2half2_rn(f.x, f.y);
        __half2 h1 = __floats2half2_rn(f.z, f.w);
        out[i] = make_uint2(*reinterpret_cast<uint32_t*>(&h0),
                            *reinterpret_cast<uint32_t*>(&h1));
    }
}

// ---------------- init / router / prefix / scatter ----------------
__global__ void init_kernel() {
    int i = threadIdx.x;
    if (i < En) { g_counts[i] = 0; g_cursor[i] = 0; }
}

__global__ void router_kernel(const float* __restrict__ x,
                              const float* __restrict__ rw,
                              const float* __restrict__ eb) {
    __shared__ float sx[Hn];
    __shared__ float ssc[En];
    int t = blockIdx.x;
    const float* xr = x + (size_t)t * Hn;
    for (int i = threadIdx.x; i < Hn; i += blockDim.x) sx[i] = xr[i];
    __syncthreads();

    int w = threadIdx.x >> 5, l = threadIdx.x & 31;
    if (w < En) {
        const float* wr = rw + (size_t)w * Hn;
        float s = 0.f;
        #pragma unroll 8
        for (int i = l; i < Hn; i += 32) s += sx[i] * wr[i];
        #pragma unroll
        for (int o = 16; o > 0; o >>= 1) s += __shfl_down_sync(0xffffffffu, s, o);
        if (l == 0) ssc[w] = s;
    }
    __syncthreads();

    if (threadIdx.x == 0) {
        float sig[En], sel[En];
        #pragma unroll
        for (int e = 0; e < En; e++) {
            sig[e] = 1.f / (1.f + expf(-ssc[e]));
            sel[e] = sig[e] + eb[e];
        }
        int idx[TOPK];
        #pragma unroll
        for (int k = 0; k < TOPK; k++) {
            int best = 0; float bv = -1e30f;
            #pragma unroll
            for (int e = 0; e < En; e++)
                if (sel[e] > bv) { bv = sel[e]; best = e; }
            idx[k] = best; sel[best] = -1e30f;
        }
        float wsum = 0.f;
        #pragma unroll
        for (int k = 0; k < TOPK; k++) wsum += sig[idx[k]];
        float inv = 1.f / (wsum + 1e-20f);
        #pragma unroll
        for (int k = 0; k < TOPK; k++) {
            g_tokExp[t * TOPK + k] = idx[k];
            g_tokW[t * TOPK + k]   = sig[idx[k]] * inv;
            atomicAdd(&g_counts[idx[k]], 1);
        }
    }
}

__global__ void prefix_kernel() {
    g_offsets[0] = 0;
    for (int e = 0; e < En; e++) g_offsets[e + 1] = g_offsets[e] + g_counts[e];
}

__global__ void scatter_kernel() {
    int t = blockIdx.x * blockDim.x + threadIdx.x;
    if (t >= Tn) return;
    #pragma unroll
    for (int k = 0; k < TOPK; k++) {
        int e = g_tokExp[t * TOPK + k];
        int pos = atomicAdd(&g_cursor[e], 1);
        int row = g_offsets[e] + pos;
        g_rowTok[row] = t;
        g_tokRow[t * TOPK + k] = row;
    }
}

// ---------------- fp16 mma.sync GEMM, cp.async 4-stage pipeline ----------------
// CTA tile 128x256x64, 8 warps (2m x 4n), warp tile 64x64, mma m16n8k16.
// SMEM rows 128B = 64 fp16 (full BK). XOR swizzle on 16B granules: g' = g ^ (row&7).
#define BM_ 128
#define BN_ 256
#define BK_ 64
#define ABYTES (BM_ * BK_ * 2)          // 16384
#define BBYTES (BN_ * BK_ * 2)          // 32768
#define STAGEB (ABYTES + BBYTES)        // 49152
#define NSTAGE 4
#define SMTOT  (NSTAGE * STAGEB)        // 196608

__global__ __launch_bounds__(256) void hmma_kernel(
    const __half* __restrict__ A, const __half* __restrict__ B, float* __restrict__ C,
    int useGather, int useCounts, int fixedM,
    int K, int ldc, int ccol, size_t bStrideZ)
{
    extern __shared__ char smem[];
    int z = blockIdx.z;
    int M, rowbase;
    if (useCounts) { M = g_counts[z]; rowbase = g_offsets[z]; }
    else           { M = fixedM;      rowbase = 0; }
    int m0 = blockIdx.y * BM_;
    if (m0 >= M) return;
    int n0 = blockIdx.x * BN_;
    const __half* Bz = B + (size_t)z * bStrideZ;

    const int tid = threadIdx.x;
    const int wid = tid >> 5, lane = tid & 31;
    const int q = lane >> 2, e = lane & 3;
    const int wm = wid & 1, wn = wid >> 1;
    const uint32_t sbase = smem_u32(smem);

    // ---- producer setup: A 4 slots, B 8 slots of 16B (8 fp16) per thread ----
    const __half* aptr[4];
    uint32_t adst[4];
    #pragma unroll
    for (int i = 0; i < 4; i++) {
        int slot = tid + i * 256;
        int row = slot >> 3, g = slot & 7;
        int gr = m0 + row;
        int cl = gr < M ? gr : (M - 1);              // clamp: garbage rows masked at store
        int src = useGather ? g_rowTok[rowbase + cl] : (rowbase + cl);
        aptr[i] = A + (size_t)src * K + g * 8;
        adst[i] = sbase + (uint32_t)(row * 128 + ((g ^ (row & 7)) << 4));
    }
    const __half* bptr[8];
    uint32_t bdst[8];
    #pragma unroll
    for (int i = 0; i < 8; i++) {
        int slot = tid + i * 256;
        int row = slot >> 3, g = slot & 7;
        bptr[i] = Bz + (size_t)(n0 + row) * K + g * 8;
        bdst[i] = sbase + (uint32_t)(ABYTES + row * 128 + ((g ^ (row & 7)) << 4));
    }

    float acc[4][8][4];
    #pragma unroll
    for (int i = 0; i < 4; i++)
        #pragma unroll
        for (int j = 0; j < 8; j++)
            #pragma unroll
            for (int v = 0; v < 4; v++) acc[i][j][v] = 0.f;

    const int nk = K / BK_;   // 32 or 12

    // ---- prologue: stages 0..NSTAGE-2 ----
    #pragma unroll
    for (int s = 0; s < NSTAGE - 1; s++) {
        uint32_t so = (uint32_t)(s * STAGEB);
        int k0 = s * BK_;
        #pragma unroll
        for (int i = 0; i < 4; i++) cp_async16(adst[i] + so, aptr[i] + k0);
        #pragma unroll
        for (int i = 0; i < 8; i++) cp_async16(bdst[i] + so, bptr[i] + k0);
        CP_COMMIT();
    }

    // ---- mainloop ----
    for (int kt = 0; kt < nk; kt++) {
        CP_WAIT(NSTAGE - 2);
        __syncthreads();

        int ns = kt + NSTAGE - 1;
        if (ns < nk) {
            uint32_t so = (uint32_t)((ns & (NSTAGE - 1)) * STAGEB);
            int k0 = ns * BK_;
            #pragma unroll
            for (int i = 0; i < 4; i++) cp_async16(adst[i] + so, aptr[i] + k0);
            #pragma unroll
            for (int i = 0; i < 8; i++) cp_async16(bdst[i] + so, bptr[i] + k0);
        }
        CP_COMMIT();

        const char* As = smem + (kt & (NSTAGE - 1)) * STAGEB;
        const char* Bs = As + ABYTES;
        const char* aBase = As + ((wm * 64 + q) * 128 + e * 4);
        const char* bBase = Bs + ((wn * 64 + q) * 128 + e * 4);

        #pragma unroll
        for (int ks = 0; ks < 4; ks++) {
            int g0 = ((2 * ks)     ^ q) << 4;
            int g1 = ((2 * ks + 1) ^ q) << 4;
            uint32_t af[4][4];
            #pragma unroll
            for (int i = 0; i < 4; i++) {
                const char* p = aBase + i * 16 * 128;
                af[i][0] = *reinterpret_cast<const uint32_t*>(p + g0);
                af[i][1] = *reinterpret_cast<const uint32_t*>(p + g0 + 8 * 128);
                af[i][2] = *reinterpret_cast<const uint32_t*>(p + g1);
                af[i][3] = *reinterpret_cast<const uint32_t*>(p + g1 + 8 * 128);
            }
            #pragma unroll
            for (int jn = 0; jn < 8; jn++) {
                const char* p = bBase + jn * 8 * 128;
                uint32_t b0 = *reinterpret_cast<const uint32_t*>(p + g0);
                uint32_t b1 = *reinterpret_cast<const uint32_t*>(p + g1);
                #pragma unroll
                for (int i = 0; i < 4; i++)
                    mma_f16(acc[i][jn][0], acc[i][jn][1], acc[i][jn][2], acc[i][jn][3],
                            af[i][0], af[i][1], af[i][2], af[i][3], b0, b1);
            }
        }
    }

    // ---- epilogue ----
    #pragma unroll
    for (int i = 0; i < 4; i++) {
        int r0 = m0 + wm * 64 + i * 16 + q;
        int r1 = r0 + 8;
        #pragma unroll
        for (int jn = 0; jn < 8; jn++) {
            int cc = ccol + n0 + wn * 64 + jn * 8 + 2 * e;
            if (r0 < M) {
                float2 v = make_float2(acc[i][jn][0], acc[i][jn][1]);
                *reinterpret_cast<float2*>(C + (size_t)(rowbase + r0) * ldc + cc) = v;
            }
            if (r1 < M) {
                float2 v = make_float2(acc[i][jn][2], acc[i][jn][3]);
                *reinterpret_cast<float2*>(C + (size_t)(rowbase + r1) * ldc + cc) = v;
            }
        }
    }
}

// ---------------- elementwise silu(g)*u -> fp16 ----------------
__global__ void silu_kernel(const float* __restrict__ gu, __half* __restrict__ mid, int rows) {
    long i = (long)blockIdx.x * blockDim.x + threadIdx.x;
    long total = (long)rows * In;
    if (i >= total) return;
    int r = (int)(i / In);
    int c = (int)(i - (long)r * In);
    float g = gu[(size_t)r * TWOI + c];
    float u = gu[(size_t)r * TWOI + In + c];
    float s = g / (1.f + expf(-g));
    mid[i] = __float2half_rn(s * u);
}

// ---------------- combine ----------------
__global__ void combine_kernel(float* __restrict__ out) {
    int t = blockIdx.x;
    int r0 = g_tokRow[t * 4 + 0], r1 = g_tokRow[t * 4 + 1];
    int r2 = g_tokRow[t * 4 + 2], r3 = g_tokRow[t * 4 + 3];
    float w0 = g_tokW[t * 4 + 0], w1 = g_tokW[t * 4 + 1];
    float w2 = g_tokW[t * 4 + 2], w3 = g_tokW[t * 4 + 3];
    const float* y0 = g_Yr + (size_t)r0 * Hn;
    const float* y1 = g_Yr + (size_t)r1 * Hn;
    const float* y2 = g_Yr + (size_t)r2 * Hn;
    const float* y3 = g_Yr + (size_t)r3 * Hn;
    float* o = out + (size_t)t * Hn;
    for (int c = threadIdx.x; c < Hn; c += blockDim.x) {
        float v = o[c];
        v += w0 * y0[c] + w1 * y1[c] + w2 * y2[c] + w3 * y3[c];
        o[c] = v;
    }
}

// ---------------- launch ----------------
extern "C" void kernel_launch(void* const* d_in, const int* in_sizes, int n_in,
                              void* d_out, int out_size) {
    const float* x    = (const float*)d_in[0];
    const float* rw   = (const float*)d_in[1];
    const float* eb   = (const float*)d_in[2];
    const float* gup  = (const float*)d_in[3];
    const float* dwn  = (const float*)d_in[4];
    const float* sgw  = (const float*)d_in[5];
    const float* suw  = (const float*)d_in[6];
    const float* sdw  = (const float*)d_in[7];
    float* out = (float*)d_out;

    static int smem_set = 0;
    if (!smem_set) {
        cudaFuncSetAttribute(hmma_kernel, cudaFuncAttributeMaxDynamicSharedMemorySize, SMTOT);
        smem_set = 1;
    }

    void *p_gu, *p_mid, *p_Yr, *p_gus, *p_mids;
    void *p_xh, *p_guph, *p_dwnh, *p_sgwh, *p_suwh, *p_sdwh;
    cudaGetSymbolAddress(&p_gu,   g_gu);
    cudaGetSymbolAddress(&p_mid,  g_mid);
    cudaGetSymbolAddress(&p_Yr,   g_Yr);
    cudaGetSymbolAddress(&p_gus,  g_gus);
    cudaGetSymbolAddress(&p_mids, g_mids);
    cudaGetSymbolAddress(&p_xh,   g_xh);
    cudaGetSymbolAddress(&p_guph, g_guph);
    cudaGetSymbolAddress(&p_dwnh, g_dwnh);
    cudaGetSymbolAddress(&p_sgwh, g_sgwh);
    cudaGetSymbolAddress(&p_suwh, g_suwh);
    cudaGetSymbolAddress(&p_sdwh, g_sdwh);

    init_kernel<<<1, 32>>>();
    router_kernel<<<Tn, 512>>>(x, rw, eb);
    prefix_kernel<<<1, 1>>>();
    scatter_kernel<<<(Tn + 255) / 256, 256>>>();

    // fp32 -> fp16 (RN) operand conversion
    const int CVB = 512, CVG = 1024;
    h16conv_kernel<<<CVG, CVB>>>((const float4*)x,   (uint2*)p_xh,   Tn * Hn / 4);
    h16conv_kernel<<<CVG, CVB>>>((const float4*)gup, (uint2*)p_guph, En * TWOI * Hn / 4);
    h16conv_kernel<<<CVG, CVB>>>((const float4*)dwn, (uint2*)p_dwnh, En * Hn * In / 4);
    h16conv_kernel<<<CVG, CVB>>>((const float4*)sgw, (uint2*)p_sgwh, In * Hn / 4);
    h16conv_kernel<<<CVG, CVB>>>((const float4*)suw, (uint2*)p_suwh, In * Hn / 4);
    h16conv_kernel<<<CVG, CVB>>>((const float4*)sdw, (uint2*)p_sdwh, Hn * In / 4);

    // routed gate_up: [8192,1536] = gather(x_h) @ gup_h^T   (K=2048)
    hmma_kernel<<<dim3(TWOI / BN_, Tn / BM_, En), 256, SMTOT>>>(
        (const __half*)p_xh, (const __half*)p_guph, (float*)p_gu,
        1, 1, 0, Hn, TWOI, 0, (size_t)TWOI * Hn);

    silu_kernel<<<(RROWS * In + 255) / 256, 256>>>((const float*)p_gu, (__half*)p_mid, RROWS);

    // routed down: [8192,2048] = mid @ dwn_h^T   (K=768)
    hmma_kernel<<<dim3(Hn / BN_, Tn / BM_, En), 256, SMTOT>>>(
        (const __half*)p_mid, (const __half*)p_dwnh, (float*)p_Yr,
        0, 1, 0, In, Hn, 0, (size_t)Hn * In);

    // shared gate / up -> gus
    hmma_kernel<<<dim3(In / BN_, Tn / BM_, 1), 256, SMTOT>>>(
        (const __half*)p_xh, (const __half*)p_sgwh, (float*)p_gus,
        0, 0, Tn, Hn, TWOI, 0, 0);
    hmma_kernel<<<dim3(In / BN_, Tn / BM_, 1), 256, SMTOT>>>(
        (const __half*)p_xh, (const __half*)p_suwh, (float*)p_gus,
        0, 0, Tn, Hn, TWOI, In, 0);

    silu_kernel<<<(Tn * In + 255) / 256, 256>>>((const float*)p_gus, (__half*)p_mids, Tn);

    // shared down -> out
    hmma_kernel<<<dim3(Hn / BN_, Tn / BM_, 1), 256, SMTOT>>>(
        (const __half*)p_mids, (const __half*)p_sdwh, out,
        0, 0, Tn, In, Hn, 0, 0);

    combine_kernel<<<Tn, 256>>>(out);
}

// round 6
// speedup vs baseline: 10.5499x; 1.1150x over previous
#include <cuda_runtime.h>
#include <cuda_fp16.h>
#include <math.h>
#include <stdint.h>

// ---------------- problem constants (fixed shapes) ----------------
#define Tn    2048
#define Hn    2048
#define En    16
#define In    768
#define TWOI  1536
#define TOPK  4
#define RROWS (Tn*TOPK)

// ---------------- device scratch ----------------
__device__ int   g_counts[En];
__device__ int   g_cursor[En];
__device__ int   g_offsets[En + 1];
__device__ int   g_rowTok[RROWS];
__device__ int   g_tokRow[Tn * TOPK];
__device__ float g_tokW[Tn * TOPK];
__device__ float g_rowW[RROWS];               // packed row -> combine weight
__device__ int   g_tokExp[Tn * TOPK];
__device__ __half g_mid [(size_t)RROWS * In];  // w * silu(g)*u (fp16)
__device__ float g_Yr  [(size_t)RROWS * Hn];   // routed down out, pre-scaled
__device__ __half g_mids[(size_t)Tn * In];     // shared silu (fp16)
// fp16 operand copies
__device__ __half g_xh  [(size_t)Tn * Hn];
__device__ __half g_guph[(size_t)En * TWOI * Hn];  // gate/up rows interleaved
__device__ __half g_dwnh[(size_t)En * Hn * In];
__device__ __half g_sguh[(size_t)TWOI * Hn];       // shared gate/up interleaved
__device__ __half g_sdwh[(size_t)Hn * In];

__device__ __forceinline__ uint32_t smem_u32(const void* p) {
    uint32_t a;
    asm("{ .reg .u64 t; cvta.to.shared.u64 t, %1; cvt.u32.u64 %0, t; }" : "=r"(a) : "l"(p));
    return a;
}

__device__ __forceinline__ void cp_async16(uint32_t dst, const void* src) {
    asm volatile("cp.async.cg.shared.global [%0], [%1], 16;" :: "r"(dst), "l"(src) : "memory");
}
#define CP_COMMIT() asm volatile("cp.async.commit_group;" ::: "memory")
#define CP_WAIT(n)  asm volatile("cp.async.wait_group %0;" :: "n"(n) : "memory")

__device__ __forceinline__ void mma_f16(float& d0, float& d1, float& d2, float& d3,
                                        uint32_t a0, uint32_t a1, uint32_t a2, uint32_t a3,
                                        uint32_t b0, uint32_t b1) {
    asm volatile(
        "mma.sync.aligned.m16n8k16.row.col.f32.f16.f16.f32 "
        "{%0,%1,%2,%3}, {%4,%5,%6,%7}, {%8,%9}, {%0,%1,%2,%3};"
        : "+f"(d0), "+f"(d1), "+f"(d2), "+f"(d3)
        : "r"(a0), "r"(a1), "r"(a2), "r"(a3), "r"(b0), "r"(b1));
}

__device__ __forceinline__ uint2 cvt4(float4 f) {
    __half2 h0 = __floats2half2_rn(f.x, f.y);
    __half2 h1 = __floats2half2_rn(f.z, f.w);
    return make_uint2(*reinterpret_cast<uint32_t*>(&h0), *reinterpret_cast<uint32_t*>(&h1));
}

// ---------------- conversion passes ----------------
__global__ void h16conv_kernel(const float4* __restrict__ in, uint2* __restrict__ out, int n4) {
    int stride = gridDim.x * blockDim.x;
    for (int i = blockIdx.x * blockDim.x + threadIdx.x; i < n4; i += stride)
        out[i] = cvt4(in[i]);
}

// gup [E, 2I, H]: out row 2j = gate row j, out row 2j+1 = up row j (per expert)
__global__ void gupconv_kernel(const float4* __restrict__ in, uint2* __restrict__ out, int n4) {
    const int HV = Hn / 4;
    int stride = gridDim.x * blockDim.x;
    for (int i = blockIdx.x * blockDim.x + threadIdx.x; i < n4; i += stride) {
        int row = i / HV, c = i - row * HV;
        int e = row / TWOI, r = row - e * TWOI;
        int src = (r & 1) ? (In + (r >> 1)) : (r >> 1);
        out[i] = cvt4(in[((size_t)e * TWOI + src) * HV + c]);
    }
}

// shared gate/up: out row 2j = sgw row j, out row 2j+1 = suw row j
__global__ void sguconv_kernel(const float4* __restrict__ gin, const float4* __restrict__ uin,
                               uint2* __restrict__ out, int n4) {
    const int HV = Hn / 4;
    int stride = gridDim.x * blockDim.x;
    for (int i = blockIdx.x * blockDim.x + threadIdx.x; i < n4; i += stride) {
        int row = i / HV, c = i - row * HV;
        int j = row >> 1;
        const float4* src = (row & 1) ? uin : gin;
        out[i] = cvt4(src[(size_t)j * HV + c]);
    }
}

// ---------------- init / router / prefix / scatter ----------------
__global__ void init_kernel() {
    int i = threadIdx.x;
    if (i < En) { g_counts[i] = 0; g_cursor[i] = 0; }
}

__global__ void router_kernel(const float* __restrict__ x,
                              const float* __restrict__ rw,
                              const float* __restrict__ eb) {
    __shared__ float sx[Hn];
    __shared__ float ssc[En];
    int t = blockIdx.x;
    const float* xr = x + (size_t)t * Hn;
    for (int i = threadIdx.x; i < Hn; i += blockDim.x) sx[i] = xr[i];
    __syncthreads();

    int w = threadIdx.x >> 5, l = threadIdx.x & 31;
    if (w < En) {
        const float* wr = rw + (size_t)w * Hn;
        float s = 0.f;
        #pragma unroll 8
        for (int i = l; i < Hn; i += 32) s += sx[i] * wr[i];
        #pragma unroll
        for (int o = 16; o > 0; o >>= 1) s += __shfl_down_sync(0xffffffffu, s, o);
        if (l == 0) ssc[w] = s;
    }
    __syncthreads();

    if (threadIdx.x == 0) {
        float sig[En], sel[En];
        #pragma unroll
        for (int e = 0; e < En; e++) {
            sig[e] = 1.f / (1.f + expf(-ssc[e]));
            sel[e] = sig[e] + eb[e];
        }
        int idx[TOPK];
        #pragma unroll
        for (int k = 0; k < TOPK; k++) {
            int best = 0; float bv = -1e30f;
            #pragma unroll
            for (int e = 0; e < En; e++)
                if (sel[e] > bv) { bv = sel[e]; best = e; }
            idx[k] = best; sel[best] = -1e30f;
        }
        float wsum = 0.f;
        #pragma unroll
        for (int k = 0; k < TOPK; k++) wsum += sig[idx[k]];
        float inv = 1.f / (wsum + 1e-20f);
        #pragma unroll
        for (int k = 0; k < TOPK; k++) {
            g_tokExp[t * TOPK + k] = idx[k];
            g_tokW[t * TOPK + k]   = sig[idx[k]] * inv;
            atomicAdd(&g_counts[idx[k]], 1);
        }
    }
}

__global__ void prefix_kernel() {
    g_offsets[0] = 0;
    for (int e = 0; e < En; e++) g_offsets[e + 1] = g_offsets[e] + g_counts[e];
}

__global__ void scatter_kernel() {
    int t = blockIdx.x * blockDim.x + threadIdx.x;
    if (t >= Tn) return;
    #pragma unroll
    for (int k = 0; k < TOPK; k++) {
        int e = g_tokExp[t * TOPK + k];
        int pos = atomicAdd(&g_cursor[e], 1);
        int row = g_offsets[e] + pos;
        g_rowTok[row] = t;
        g_tokRow[t * TOPK + k] = row;
        g_rowW[row] = g_tokW[t * TOPK + k];
    }
}

// ---------------- fp16 mma.sync GEMM, cp.async 4-stage pipeline ----------------
// CTA tile 128x256x64, 8 warps (2m x 4n), warp tile 64x64, mma m16n8k16.
// fuseSilu: columns are interleaved (g,u) pairs; epilogue writes w*silu(g)*u fp16.
#define BM_ 128
#define BN_ 256
#define BK_ 64
#define ABYTES (BM_ * BK_ * 2)
#define BBYTES (BN_ * BK_ * 2)
#define STAGEB (ABYTES + BBYTES)
#define NSTAGE 4
#define SMTOT  (NSTAGE * STAGEB)        // 196608

__global__ __launch_bounds__(256) void hmma_kernel(
    const __half* __restrict__ A, const __half* __restrict__ B, void* __restrict__ Cv,
    int useGather, int useCounts, int fixedM, int fuseSilu,
    int K, int ldc, int ccol, size_t bStrideZ)
{
    extern __shared__ char smem[];
    int z = blockIdx.z;
    int M, rowbase;
    if (useCounts) { M = g_counts[z]; rowbase = g_offsets[z]; }
    else           { M = fixedM;      rowbase = 0; }
    int m0 = blockIdx.y * BM_;
    if (m0 >= M) return;
    int n0 = blockIdx.x * BN_;
    const __half* Bz = B + (size_t)z * bStrideZ;

    const int tid = threadIdx.x;
    const int wid = tid >> 5, lane = tid & 31;
    const int q = lane >> 2, e = lane & 3;
    const int wm = wid & 1, wn = wid >> 1;
    const uint32_t sbase = smem_u32(smem);

    const __half* aptr[4];
    uint32_t adst[4];
    #pragma unroll
    for (int i = 0; i < 4; i++) {
        int slot = tid + i * 256;
        int row = slot >> 3, g = slot & 7;
        int gr = m0 + row;
        int cl = gr < M ? gr : (M - 1);
        int src = useGather ? g_rowTok[rowbase + cl] : (rowbase + cl);
        aptr[i] = A + (size_t)src * K + g * 8;
        adst[i] = sbase + (uint32_t)(row * 128 + ((g ^ (row & 7)) << 4));
    }
    const __half* bptr[8];
    uint32_t bdst[8];
    #pragma unroll
    for (int i = 0; i < 8; i++) {
        int slot = tid + i * 256;
        int row = slot >> 3, g = slot & 7;
        bptr[i] = Bz + (size_t)(n0 + row) * K + g * 8;
        bdst[i] = sbase + (uint32_t)(ABYTES + row * 128 + ((g ^ (row & 7)) << 4));
    }

    float acc[4][8][4];
    #pragma unroll
    for (int i = 0; i < 4; i++)
        #pragma unroll
        for (int j = 0; j < 8; j++)
            #pragma unroll
            for (int v = 0; v < 4; v++) acc[i][j][v] = 0.f;

    const int nk = K / BK_;

    #pragma unroll
    for (int s = 0; s < NSTAGE - 1; s++) {
        uint32_t so = (uint32_t)(s * STAGEB);
        int k0 = s * BK_;
        #pragma unroll
        for (int i = 0; i < 4; i++) cp_async16(adst[i] + so, aptr[i] + k0);
        #pragma unroll
        for (int i = 0; i < 8; i++) cp_async16(bdst[i] + so, bptr[i] + k0);
        CP_COMMIT();
    }

    for (int kt = 0; kt < nk; kt++) {
        CP_WAIT(NSTAGE - 2);
        __syncthreads();

        int ns = kt + NSTAGE - 1;
        if (ns < nk) {
            uint32_t so = (uint32_t)((ns & (NSTAGE - 1)) * STAGEB);
            int k0 = ns * BK_;
            #pragma unroll
            for (int i = 0; i < 4; i++) cp_async16(adst[i] + so, aptr[i] + k0);
            #pragma unroll
            for (int i = 0; i < 8; i++) cp_async16(bdst[i] + so, bptr[i] + k0);
        }
        CP_COMMIT();

        const char* As = smem + (kt & (NSTAGE - 1)) * STAGEB;
        const char* Bs = As + ABYTES;
        const char* aBase = As + ((wm * 64 + q) * 128 + e * 4);
        const char* bBase = Bs + ((wn * 64 + q) * 128 + e * 4);

        #pragma unroll
        for (int ks = 0; ks < 4; ks++) {
            int g0 = ((2 * ks)     ^ q) << 4;
            int g1 = ((2 * ks + 1) ^ q) << 4;
            uint32_t af[4][4];
            #pragma unroll
            for (int i = 0; i < 4; i++) {
                const char* p = aBase + i * 16 * 128;
                af[i][0] = *reinterpret_cast<const uint32_t*>(p + g0);
                af[i][1] = *reinterpret_cast<const uint32_t*>(p + g0 + 8 * 128);
                af[i][2] = *reinterpret_cast<const uint32_t*>(p + g1);
                af[i][3] = *reinterpret_cast<const uint32_t*>(p + g1 + 8 * 128);
            }
            #pragma unroll
            for (int jn = 0; jn < 8; jn++) {
                const char* p = bBase + jn * 8 * 128;
                uint32_t b0 = *reinterpret_cast<const uint32_t*>(p + g0);
                uint32_t b1 = *reinterpret_cast<const uint32_t*>(p + g1);
                #pragma unroll
                for (int i = 0; i < 4; i++)
                    mma_f16(acc[i][jn][0], acc[i][jn][1], acc[i][jn][2], acc[i][jn][3],
                            af[i][0], af[i][1], af[i][2], af[i][3], b0, b1);
            }
        }
    }

    // ---- epilogue ----
    if (fuseSilu) {
        __half* Ch = (__half*)Cv;
        #pragma unroll
        for (int i = 0; i < 4; i++) {
            int r0 = m0 + wm * 64 + i * 16 + q;
            int r1 = r0 + 8;
            float w0 = 1.f, w1 = 1.f;
            if (useCounts) {
                if (r0 < M) w0 = g_rowW[rowbase + r0];
                if (r1 < M) w1 = g_rowW[rowbase + r1];
            }
            #pragma unroll
            for (int jn = 0; jn < 8; jn++) {
                int j = (n0 + wn * 64 + jn * 8 + 2 * e) >> 1;   // (g,u) pair index
                if (r0 < M) {
                    float g = acc[i][jn][0], u = acc[i][jn][1];
                    float s = g / (1.f + expf(-g));
                    Ch[(size_t)(rowbase + r0) * ldc + j] = __float2half_rn(w0 * s * u);
                }
                if (r1 < M) {
                    float g = acc[i][jn][2], u = acc[i][jn][3];
                    float s = g / (1.f + expf(-g));
                    Ch[(size_t)(rowbase + r1) * ldc + j] = __float2half_rn(w1 * s * u);
                }
            }
        }
    } else {
        float* C = (float*)Cv;
        #pragma unroll
        for (int i = 0; i < 4; i++) {
            int r0 = m0 + wm * 64 + i * 16 + q;
            int r1 = r0 + 8;
            #pragma unroll
            for (int jn = 0; jn < 8; jn++) {
                int cc = ccol + n0 + wn * 64 + jn * 8 + 2 * e;
                if (r0 < M) {
                    float2 v = make_float2(acc[i][jn][0], acc[i][jn][1]);
                    *reinterpret_cast<float2*>(C + (size_t)(rowbase + r0) * ldc + cc) = v;
                }
                if (r1 < M) {
                    float2 v = make_float2(acc[i][jn][2], acc[i][jn][3]);
                    *reinterpret_cast<float2*>(C + (size_t)(rowbase + r1) * ldc + cc) = v;
                }
            }
        }
    }
}

// ---------------- combine: out[t] += sum_k Yr[row_k]  (weights pre-applied) ----------------
__global__ void combine_kernel(float* __restrict__ out) {
    int t = blockIdx.x;
    int r0 = g_tokRow[t * 4 + 0], r1 = g_tokRow[t * 4 + 1];
    int r2 = g_tokRow[t * 4 + 2], r3 = g_tokRow[t * 4 + 3];
    const float* y0 = g_Yr + (size_t)r0 * Hn;
    const float* y1 = g_Yr + (size_t)r1 * Hn;
    const float* y2 = g_Yr + (size_t)r2 * Hn;
    const float* y3 = g_Yr + (size_t)r3 * Hn;
    float* o = out + (size_t)t * Hn;
    for (int c = threadIdx.x; c < Hn; c += blockDim.x) {
        o[c] = o[c] + y0[c] + y1[c] + y2[c] + y3[c];
    }
}

// ---------------- launch ----------------
extern "C" void kernel_launch(void* const* d_in, const int* in_sizes, int n_in,
                              void* d_out, int out_size) {
    const float* x    = (const float*)d_in[0];
    const float* rw   = (const float*)d_in[1];
    const float* eb   = (const float*)d_in[2];
    const float* gup  = (const float*)d_in[3];
    const float* dwn  = (const float*)d_in[4];
    const float* sgw  = (const float*)d_in[5];
    const float* suw  = (const float*)d_in[6];
    const float* sdw  = (const float*)d_in[7];
    float* out = (float*)d_out;

    static int smem_set = 0;
    if (!smem_set) {
        cudaFuncSetAttribute(hmma_kernel, cudaFuncAttributeMaxDynamicSharedMemorySize, SMTOT);
        smem_set = 1;
    }

    void *p_mid, *p_Yr, *p_mids;
    void *p_xh, *p_guph, *p_dwnh, *p_sguh, *p_sdwh;
    cudaGetSymbolAddress(&p_mid,  g_mid);
    cudaGetSymbolAddress(&p_Yr,   g_Yr);
    cudaGetSymbolAddress(&p_mids, g_mids);
    cudaGetSymbolAddress(&p_xh,   g_xh);
    cudaGetSymbolAddress(&p_guph, g_guph);
    cudaGetSymbolAddress(&p_dwnh, g_dwnh);
    cudaGetSymbolAddress(&p_sguh, g_sguh);
    cudaGetSymbolAddress(&p_sdwh, g_sdwh);

    init_kernel<<<1, 32>>>();
    router_kernel<<<Tn, 512>>>(x, rw, eb);
    prefix_kernel<<<1, 1>>>();
    scatter_kernel<<<(Tn + 255) / 256, 256>>>();

    // fp32 -> fp16 (RN) operand conversion (+ gate/up interleave)
    const int CVB = 512, CVG = 1024;
    h16conv_kernel<<<CVG, CVB>>>((const float4*)x,   (uint2*)p_xh,   Tn * Hn / 4);
    gupconv_kernel<<<CVG, CVB>>>((const float4*)gup, (uint2*)p_guph, En * TWOI * Hn / 4);
    h16conv_kernel<<<CVG, CVB>>>((const float4*)dwn, (uint2*)p_dwnh, En * Hn * In / 4);
    sguconv_kernel<<<CVG, CVB>>>((const float4*)sgw, (const float4*)suw,
                                 (uint2*)p_sguh, TWOI * Hn / 4);
    h16conv_kernel<<<CVG, CVB>>>((const float4*)sdw, (uint2*)p_sdwh, Hn * In / 4);

    // routed gate_up + fused SwiGLU + weight: mid[8192, 768] fp16   (K=2048)
    hmma_kernel<<<dim3(TWOI / BN_, Tn / BM_, En), 256, SMTOT>>>(
        (const __half*)p_xh, (const __half*)p_guph, p_mid,
        1, 1, 0, /*fuseSilu=*/1, Hn, /*ldc=*/In, 0, (size_t)TWOI * Hn);

    // routed down: Yr[8192, 2048] = mid @ dwn_h^T   (K=768)
    hmma_kernel<<<dim3(Hn / BN_, Tn / BM_, En), 256, SMTOT>>>(
        (const __half*)p_mid, (const __half*)p_dwnh, p_Yr,
        0, 1, 0, 0, In, Hn, 0, (size_t)Hn * In);

    // shared gate+up (merged, interleaved) + fused SwiGLU: mids[2048, 768] fp16
    hmma_kernel<<<dim3(TWOI / BN_, Tn / BM_, 1), 256, SMTOT>>>(
        (const __half*)p_xh, (const __half*)p_sguh, p_mids,
        0, 0, Tn, /*fuseSilu=*/1, Hn, /*ldc=*/In, 0, 0);

    // shared down -> out
    hmma_kernel<<<dim3(Hn / BN_, Tn / BM_, 1), 256, SMTOT>>>(
        (const __half*)p_mids, (const __half*)p_sdwh, out,
        0, 0, Tn, 0, In, Hn, 0, 0);

    combine_kernel<<<Tn, 256>>>(out);
}

// round 7
// speedup vs baseline: 12.0898x; 1.1460x over previous
#include <cuda_runtime.h>
#include <cuda_fp16.h>
#include <math.h>
#include <stdint.h>

// ---------------- problem constants (fixed shapes) ----------------
#define Tn    2048
#define Hn    2048
#define En    16
#define In    768
#define TWOI  1536
#define TOPK  4
#define RROWS (Tn*TOPK)

// ---------------- device scratch ----------------
__device__ int   g_counts[En];
__device__ int   g_cursor[En];
__device__ int   g_offsets[En + 1];
__device__ int   g_rowTok[RROWS];
__device__ int   g_tokRow[Tn * TOPK];
__device__ float g_tokW[Tn * TOPK];
__device__ float g_rowW[RROWS];
__device__ int   g_tokExp[Tn * TOPK];
__device__ __half g_mid [(size_t)RROWS * In];
__device__ float g_Yr  [(size_t)RROWS * Hn];
__device__ __half g_mids[(size_t)Tn * In];
// fp16 operand copies
__device__ __half g_xh  [(size_t)Tn * Hn];
__device__ __half g_guph[(size_t)En * TWOI * Hn];
__device__ __half g_dwnh[(size_t)En * Hn * In];
__device__ __half g_sguh[(size_t)TWOI * Hn];
__device__ __half g_sdwh[(size_t)Hn * In];

__device__ __forceinline__ uint32_t smem_u32(const void* p) {
    uint32_t a;
    asm("{ .reg .u64 t; cvta.to.shared.u64 t, %1; cvt.u32.u64 %0, t; }" : "=r"(a) : "l"(p));
    return a;
}

__device__ __forceinline__ void cp_async16(uint32_t dst, const void* src) {
    asm volatile("cp.async.cg.shared.global [%0], [%1], 16;" :: "r"(dst), "l"(src) : "memory");
}
#define CP_COMMIT() asm volatile("cp.async.commit_group;" ::: "memory")
#define CP_WAIT(n)  asm volatile("cp.async.wait_group %0;" :: "n"(n) : "memory")

__device__ __forceinline__ void mma_f16(float& d0, float& d1, float& d2, float& d3,
                                        uint32_t a0, uint32_t a1, uint32_t a2, uint32_t a3,
                                        uint32_t b0, uint32_t b1) {
    asm volatile(
        "mma.sync.aligned.m16n8k16.row.col.f32.f16.f16.f32 "
        "{%0,%1,%2,%3}, {%4,%5,%6,%7}, {%8,%9}, {%0,%1,%2,%3};"
        : "+f"(d0), "+f"(d1), "+f"(d2), "+f"(d3)
        : "r"(a0), "r"(a1), "r"(a2), "r"(a3), "r"(b0), "r"(b1));
}

__device__ __forceinline__ uint2 cvt4(float4 f) {
    __half2 h0 = __floats2half2_rn(f.x, f.y);
    __half2 h1 = __floats2half2_rn(f.z, f.w);
    return make_uint2(*reinterpret_cast<uint32_t*>(&h0), *reinterpret_cast<uint32_t*>(&h1));
}

// ---------------- conversion passes ----------------
__global__ void h16conv_kernel(const float4* __restrict__ in, uint2* __restrict__ out, int n4) {
    int stride = gridDim.x * blockDim.x;
    for (int i = blockIdx.x * blockDim.x + threadIdx.x; i < n4; i += stride)
        out[i] = cvt4(in[i]);
}

__global__ void gupconv_kernel(const float4* __restrict__ in, uint2* __restrict__ out, int n4) {
    const int HV = Hn / 4;
    int stride = gridDim.x * blockDim.x;
    for (int i = blockIdx.x * blockDim.x + threadIdx.x; i < n4; i += stride) {
        int row = i / HV, c = i - row * HV;
        int e = row / TWOI, r = row - e * TWOI;
        int src = (r & 1) ? (In + (r >> 1)) : (r >> 1);
        out[i] = cvt4(in[((size_t)e * TWOI + src) * HV + c]);
    }
}

__global__ void sguconv_kernel(const float4* __restrict__ gin, const float4* __restrict__ uin,
                               uint2* __restrict__ out, int n4) {
    const int HV = Hn / 4;
    int stride = gridDim.x * blockDim.x;
    for (int i = blockIdx.x * blockDim.x + threadIdx.x; i < n4; i += stride) {
        int row = i / HV, c = i - row * HV;
        int j = row >> 1;
        const float4* src = (row & 1) ? uin : gin;
        out[i] = cvt4(src[(size_t)j * HV + c]);
    }
}

// ---------------- init / router / prefix / scatter ----------------
__global__ void init_kernel() {
    int i = threadIdx.x;
    if (i < En) { g_counts[i] = 0; g_cursor[i] = 0; }
}

__global__ void router_kernel(const float* __restrict__ x,
                              const float* __restrict__ rw,
                              const float* __restrict__ eb) {
    __shared__ float sx[Hn];
    __shared__ float ssc[En];
    int t = blockIdx.x;
    const float* xr = x + (size_t)t * Hn;
    for (int i = threadIdx.x; i < Hn; i += blockDim.x) sx[i] = xr[i];
    __syncthreads();

    int w = threadIdx.x >> 5, l = threadIdx.x & 31;
    if (w < En) {
        const float* wr = rw + (size_t)w * Hn;
        float s = 0.f;
        #pragma unroll 8
        for (int i = l; i < Hn; i += 32) s += sx[i] * wr[i];
        #pragma unroll
        for (int o = 16; o > 0; o >>= 1) s += __shfl_down_sync(0xffffffffu, s, o);
        if (l == 0) ssc[w] = s;
    }
    __syncthreads();

    if (threadIdx.x == 0) {
        float sig[En], sel[En];
        #pragma unroll
        for (int e = 0; e < En; e++) {
            sig[e] = 1.f / (1.f + expf(-ssc[e]));
            sel[e] = sig[e] + eb[e];
        }
        int idx[TOPK];
        #pragma unroll
        for (int k = 0; k < TOPK; k++) {
            int best = 0; float bv = -1e30f;
            #pragma unroll
            for (int e = 0; e < En; e++)
                if (sel[e] > bv) { bv = sel[e]; best = e; }
            idx[k] = best; sel[best] = -1e30f;
        }
        float wsum = 0.f;
        #pragma unroll
        for (int k = 0; k < TOPK; k++) wsum += sig[idx[k]];
        float inv = 1.f / (wsum + 1e-20f);
        #pragma unroll
        for (int k = 0; k < TOPK; k++) {
            g_tokExp[t * TOPK + k] = idx[k];
            g_tokW[t * TOPK + k]   = sig[idx[k]] * inv;
            atomicAdd(&g_counts[idx[k]], 1);
        }
    }
}

__global__ void prefix_kernel() {
    g_offsets[0] = 0;
    for (int e = 0; e < En; e++) g_offsets[e + 1] = g_offsets[e] + g_counts[e];
}

__global__ void scatter_kernel() {
    int t = blockIdx.x * blockDim.x + threadIdx.x;
    if (t >= Tn) return;
    #pragma unroll
    for (int k = 0; k < TOPK; k++) {
        int e = g_tokExp[t * TOPK + k];
        int pos = atomicAdd(&g_cursor[e], 1);
        int row = g_offsets[e] + pos;
        g_rowTok[row] = t;
        g_tokRow[t * TOPK + k] = row;
        g_rowW[row] = g_tokW[t * TOPK + k];
    }
}

// ---------------- fp16 mma.sync GEMM, cp.async 4-stage pipeline ----------------
#define BM_ 128
#define BN_ 256
#define BK_ 64
#define ABYTES (BM_ * BK_ * 2)
#define BBYTES (BN_ * BK_ * 2)
#define STAGEB (ABYTES + BBYTES)
#define NSTAGE 4
#define SMTOT  (NSTAGE * STAGEB)        // 196608

__global__ __launch_bounds__(256) void hmma_kernel(
    const __half* __restrict__ A, const __half* __restrict__ B, void* __restrict__ Cv,
    int useGather, int useCounts, int fixedM, int fuseSilu,
    int K, int ldc, int ccol, size_t bStrideZ)
{
    extern __shared__ char smem[];
    int z = blockIdx.z;
    int M, rowbase;
    if (useCounts) { M = g_counts[z]; rowbase = g_offsets[z]; }
    else           { M = fixedM;      rowbase = 0; }
    int m0 = blockIdx.y * BM_;
    if (m0 >= M) return;
    int n0 = blockIdx.x * BN_;
    const __half* Bz = B + (size_t)z * bStrideZ;

    const int tid = threadIdx.x;
    const int wid = tid >> 5, lane = tid & 31;
    const int q = lane >> 2, e = lane & 3;
    const int wm = wid & 1, wn = wid >> 1;
    const uint32_t sbase = smem_u32(smem);

    const __half* aptr[4];
    uint32_t adst[4];
    #pragma unroll
    for (int i = 0; i < 4; i++) {
        int slot = tid + i * 256;
        int row = slot >> 3, g = slot & 7;
        int gr = m0 + row;
        int cl = gr < M ? gr : (M - 1);
        int src = useGather ? g_rowTok[rowbase + cl] : (rowbase + cl);
        aptr[i] = A + (size_t)src * K + g * 8;
        adst[i] = sbase + (uint32_t)(row * 128 + ((g ^ (row & 7)) << 4));
    }
    const __half* bptr[8];
    uint32_t bdst[8];
    #pragma unroll
    for (int i = 0; i < 8; i++) {
        int slot = tid + i * 256;
        int row = slot >> 3, g = slot & 7;
        bptr[i] = Bz + (size_t)(n0 + row) * K + g * 8;
        bdst[i] = sbase + (uint32_t)(ABYTES + row * 128 + ((g ^ (row & 7)) << 4));
    }

    float acc[4][8][4];
    #pragma unroll
    for (int i = 0; i < 4; i++)
        #pragma unroll
        for (int j = 0; j < 8; j++)
            #pragma unroll
            for (int v = 0; v < 4; v++) acc[i][j][v] = 0.f;

    const int nk = K / BK_;

    #pragma unroll
    for (int s = 0; s < NSTAGE - 1; s++) {
        uint32_t so = (uint32_t)(s * STAGEB);
        int k0 = s * BK_;
        #pragma unroll
        for (int i = 0; i < 4; i++) cp_async16(adst[i] + so, aptr[i] + k0);
        #pragma unroll
        for (int i = 0; i < 8; i++) cp_async16(bdst[i] + so, bptr[i] + k0);
        CP_COMMIT();
    }

    for (int kt = 0; kt < nk; kt++) {
        CP_WAIT(NSTAGE - 2);
        __syncthreads();

        int ns = kt + NSTAGE - 1;
        if (ns < nk) {
            uint32_t so = (uint32_t)((ns & (NSTAGE - 1)) * STAGEB);
            int k0 = ns * BK_;
            #pragma unroll
            for (int i = 0; i < 4; i++) cp_async16(adst[i] + so, aptr[i] + k0);
            #pragma unroll
            for (int i = 0; i < 8; i++) cp_async16(bdst[i] + so, bptr[i] + k0);
        }
        CP_COMMIT();

        const char* As = smem + (kt & (NSTAGE - 1)) * STAGEB;
        const char* Bs = As + ABYTES;
        const char* aBase = As + ((wm * 64 + q) * 128 + e * 4);
        const char* bBase = Bs + ((wn * 64 + q) * 128 + e * 4);

        #pragma unroll
        for (int ks = 0; ks < 4; ks++) {
            int g0 = ((2 * ks)     ^ q) << 4;
            int g1 = ((2 * ks + 1) ^ q) << 4;
            uint32_t af[4][4];
            #pragma unroll
            for (int i = 0; i < 4; i++) {
                const char* p = aBase + i * 16 * 128;
                af[i][0] = *reinterpret_cast<const uint32_t*>(p + g0);
                af[i][1] = *reinterpret_cast<const uint32_t*>(p + g0 + 8 * 128);
                af[i][2] = *reinterpret_cast<const uint32_t*>(p + g1);
                af[i][3] = *reinterpret_cast<const uint32_t*>(p + g1 + 8 * 128);
            }
            #pragma unroll
            for (int jn = 0; jn < 8; jn++) {
                const char* p = bBase + jn * 8 * 128;
                uint32_t b0 = *reinterpret_cast<const uint32_t*>(p + g0);
                uint32_t b1 = *reinterpret_cast<const uint32_t*>(p + g1);
                #pragma unroll
                for (int i = 0; i < 4; i++)
                    mma_f16(acc[i][jn][0], acc[i][jn][1], acc[i][jn][2], acc[i][jn][3],
                            af[i][0], af[i][1], af[i][2], af[i][3], b0, b1);
            }
        }
    }

    // ---- epilogue ----
    if (fuseSilu) {
        __half* Ch = (__half*)Cv;
        #pragma unroll
        for (int i = 0; i < 4; i++) {
            int r0 = m0 + wm * 64 + i * 16 + q;
            int r1 = r0 + 8;
            float w0 = 1.f, w1 = 1.f;
            if (useCounts) {
                if (r0 < M) w0 = g_rowW[rowbase + r0];
                if (r1 < M) w1 = g_rowW[rowbase + r1];
            }
            #pragma unroll
            for (int jn = 0; jn < 8; jn++) {
                int j = (n0 + wn * 64 + jn * 8 + 2 * e) >> 1;
                if (r0 < M) {
                    float g = acc[i][jn][0], u = acc[i][jn][1];
                    float s = g / (1.f + expf(-g));
                    Ch[(size_t)(rowbase + r0) * ldc + j] = __float2half_rn(w0 * s * u);
                }
                if (r1 < M) {
                    float g = acc[i][jn][2], u = acc[i][jn][3];
                    float s = g / (1.f + expf(-g));
                    Ch[(size_t)(rowbase + r1) * ldc + j] = __float2half_rn(w1 * s * u);
                }
            }
        }
    } else {
        float* C = (float*)Cv;
        #pragma unroll
        for (int i = 0; i < 4; i++) {
            int r0 = m0 + wm * 64 + i * 16 + q;
            int r1 = r0 + 8;
            #pragma unroll
            for (int jn = 0; jn < 8; jn++) {
                int cc = ccol + n0 + wn * 64 + jn * 8 + 2 * e;
                if (r0 < M) {
                    float2 v = make_float2(acc[i][jn][0], acc[i][jn][1]);
                    *reinterpret_cast<float2*>(C + (size_t)(rowbase + r0) * ldc + cc) = v;
                }
                if (r1 < M) {
                    float2 v = make_float2(acc[i][jn][2], acc[i][jn][3]);
                    *reinterpret_cast<float2*>(C + (size_t)(rowbase + r1) * ldc + cc) = v;
                }
            }
        }
    }
}

// ---------------- combine ----------------
__global__ void combine_kernel(float* __restrict__ out) {
    int t = blockIdx.x;
    int r0 = g_tokRow[t * 4 + 0], r1 = g_tokRow[t * 4 + 1];
    int r2 = g_tokRow[t * 4 + 2], r3 = g_tokRow[t * 4 + 3];
    const float* y0 = g_Yr + (size_t)r0 * Hn;
    const float* y1 = g_Yr + (size_t)r1 * Hn;
    const float* y2 = g_Yr + (size_t)r2 * Hn;
    const float* y3 = g_Yr + (size_t)r3 * Hn;
    float* o = out + (size_t)t * Hn;
    for (int c = threadIdx.x; c < Hn; c += blockDim.x) {
        o[c] = o[c] + y0[c] + y1[c] + y2[c] + y3[c];
    }
}

// ---------------- launch (fork-join multi-stream graph) ----------------
extern "C" void kernel_launch(void* const* d_in, const int* in_sizes, int n_in,
                              void* d_out, int out_size) {
    const float* x    = (const float*)d_in[0];
    const float* rw   = (const float*)d_in[1];
    const float* eb   = (const float*)d_in[2];
    const float* gup  = (const float*)d_in[3];
    const float* dwn  = (const float*)d_in[4];
    const float* sgw  = (const float*)d_in[5];
    const float* suw  = (const float*)d_in[6];
    const float* sdw  = (const float*)d_in[7];
    float* out = (float*)d_out;

    static int inited = 0;
    static cudaStream_t s1, s2;
    static cudaEvent_t evRoot, evXh, evGup, evDwn, evShared;
    if (!inited) {
        cudaFuncSetAttribute(hmma_kernel, cudaFuncAttributeMaxDynamicSharedMemorySize, SMTOT);
        cudaStreamCreateWithFlags(&s1, cudaStreamNonBlocking);
        cudaStreamCreateWithFlags(&s2, cudaStreamNonBlocking);
        cudaEventCreateWithFlags(&evRoot,   cudaEventDisableTiming);
        cudaEventCreateWithFlags(&evXh,     cudaEventDisableTiming);
        cudaEventCreateWithFlags(&evGup,    cudaEventDisableTiming);
        cudaEventCreateWithFlags(&evDwn,    cudaEventDisableTiming);
        cudaEventCreateWithFlags(&evShared, cudaEventDisableTiming);
        inited = 1;
    }

    void *p_mid, *p_Yr, *p_mids;
    void *p_xh, *p_guph, *p_dwnh, *p_sguh, *p_sdwh;
    cudaGetSymbolAddress(&p_mid,  g_mid);
    cudaGetSymbolAddress(&p_Yr,   g_Yr);
    cudaGetSymbolAddress(&p_mids, g_mids);
    cudaGetSymbolAddress(&p_xh,   g_xh);
    cudaGetSymbolAddress(&p_guph, g_guph);
    cudaGetSymbolAddress(&p_dwnh, g_dwnh);
    cudaGetSymbolAddress(&p_sguh, g_sguh);
    cudaGetSymbolAddress(&p_sdwh, g_sdwh);

    const int CVB = 512, CVG = 1024;

    // ---- fork ----
    cudaEventRecord(evRoot, 0);
    cudaStreamWaitEvent(s1, evRoot, 0);
    cudaStreamWaitEvent(s2, evRoot, 0);

    // main stream: routing chain
    init_kernel<<<1, 32>>>();
    router_kernel<<<Tn, 512>>>(x, rw, eb);
    prefix_kernel<<<1, 1>>>();
    scatter_kernel<<<(Tn + 255) / 256, 256>>>();

    // s1: conversions on the routed critical path (xh, guph) then dwn
    h16conv_kernel<<<CVG, CVB, 0, s1>>>((const float4*)x, (uint2*)p_xh, Tn * Hn / 4);
    cudaEventRecord(evXh, s1);
    gupconv_kernel<<<CVG, CVB, 0, s1>>>((const float4*)gup, (uint2*)p_guph, En * TWOI * Hn / 4);
    cudaEventRecord(evGup, s1);
    h16conv_kernel<<<CVG, CVB, 0, s1>>>((const float4*)dwn, (uint2*)p_dwnh, En * Hn * In / 4);
    cudaEventRecord(evDwn, s1);

    // s2: shared-expert chain (convs + both GEMMs), writes `out`
    sguconv_kernel<<<CVG, CVB, 0, s2>>>((const float4*)sgw, (const float4*)suw,
                                        (uint2*)p_sguh, TWOI * Hn / 4);
    h16conv_kernel<<<CVG, CVB, 0, s2>>>((const float4*)sdw, (uint2*)p_sdwh, Hn * In / 4);
    cudaStreamWaitEvent(s2, evXh, 0);
    hmma_kernel<<<dim3(TWOI / BN_, Tn / BM_, 1), 256, SMTOT, s2>>>(
        (const __half*)p_xh, (const __half*)p_sguh, p_mids,
        0, 0, Tn, /*fuseSilu=*/1, Hn, /*ldc=*/In, 0, 0);
    hmma_kernel<<<dim3(Hn / BN_, Tn / BM_, 1), 256, SMTOT, s2>>>(
        (const __half*)p_mids, (const __half*)p_sdwh, out,
        0, 0, Tn, 0, In, Hn, 0, 0);
    cudaEventRecord(evShared, s2);

    // main stream: routed GEMM chain
    cudaStreamWaitEvent(0, evXh, 0);
    cudaStreamWaitEvent(0, evGup, 0);
    hmma_kernel<<<dim3(TWOI / BN_, Tn / BM_, En), 256, SMTOT>>>(
        (const __half*)p_xh, (const __half*)p_guph, p_mid,
        1, 1, 0, /*fuseSilu=*/1, Hn, /*ldc=*/In, 0, (size_t)TWOI * Hn);

    cudaStreamWaitEvent(0, evDwn, 0);
    hmma_kernel<<<dim3(Hn / BN_, Tn / BM_, En), 256, SMTOT>>>(
        (const __half*)p_mid, (const __half*)p_dwnh, p_Yr,
        0, 1, 0, 0, In, Hn, 0, (size_t)Hn * In);

    // join: combine needs out (s2) + Yr (main)
    cudaStreamWaitEvent(0, evShared, 0);
    combine_kernel<<<Tn, 256>>>(out);
}